// round 11
// baseline (speedup 1.0000x reference)
#include <cuda_runtime.h>
#include <cuda_fp16.h>
#include <math.h>

// Problem constants
#define NG    2048
#define NPG   512
#define CPG   128
#define CPG2  32

// Output layout (float32)
#define OFF_ZWHAT 0
#define OFF_ZMASK 131072
#define OFF_MU    262144
#define OFF_SIGMA 524288
#define OFF_F     786432

struct __align__(16) Smem {
    float w1l[64];      // [4][16]
    float b1l[16];
    float b1g[32];
    float b2l[64];
    float w1g[512];     // [16][32]
    float pos1l[2][384];
    float pos2l2[192];  // [2][32][3]
    int   idx1[2][128];
    int   cur[2][128];
    int   cur2[2][32];
    unsigned short ofs[2][128];
    unsigned short ofs2[2][32];
    unsigned short order[2][512];
    unsigned short order2[2][128];
    float agg[2][2048];     // stage1 means [128][16]
    __half2 mean2h[2048];   // [2][32][32h2]
    float gsum[256];
    float fvec[512];
    float outv[512];
    union {                 // 8 KB
        __half2 f1h[2][2048];   // [128][16h2] per glimpse
        float   psum[2048];     // [2][8][128]
    } A;
    union {                 // 16 KB
        float4  pts[2][512];
        __half2 h2[2][4096];    // [128][32h2] per glimpse
        __half2 f2h[4096];      // [2][32][64h2]
    } B;
};

typedef unsigned long long u64t;

__device__ __forceinline__ float celu1(float x) {
    return fmaxf(x, 0.0f) + (__expf(fminf(x, 0.0f)) - 1.0f);
}

// ---- packed fp32x2 helpers (Blackwell FFMA2) ----
__device__ __forceinline__ u64t splat2(float x) {
    u64t r; asm("mov.b64 %0, {%1, %1};" : "=l"(r) : "f"(x)); return r;
}
__device__ __forceinline__ u64t pack2(float lo, float hi) {
    u64t r; asm("mov.b64 %0, {%1, %2};" : "=l"(r) : "f"(lo), "f"(hi)); return r;
}
__device__ __forceinline__ void unpack2(u64t v, float& lo, float& hi) {
    asm("mov.b64 {%0, %1}, %2;" : "=f"(lo), "=f"(hi) : "l"(v));
}
__device__ __forceinline__ void ffma2(u64t& acc, u64t a, u64t b) {
    asm("fma.rn.f32x2 %0, %1, %2, %0;" : "+l"(acc) : "l"(a), "l"(b));
}
#define FMA2P(accp, xs2, wv2) \
    { ffma2((accp)[0], (xs2), (wv2).x); ffma2((accp)[1], (xs2), (wv2).y); }

#define FMA4(Aacc, xs, wv) \
    { Aacc[0] = fmaf((xs), (wv).x, Aacc[0]); Aacc[1] = fmaf((xs), (wv).y, Aacc[1]); \
      Aacc[2] = fmaf((xs), (wv).z, Aacc[2]); Aacc[3] = fmaf((xs), (wv).w, Aacc[3]); }

__device__ __forceinline__ void pack2h2(float a0, float a1, float a2, float a3,
                                        __half2* dst) {
    const __half2 h0 = __floats2half2_rn(a0, a1);
    const __half2 h1 = __floats2half2_rn(a2, a3);
    float2 pk;
    pk.x = __uint_as_float(*reinterpret_cast<const unsigned int*>(&h0));
    pk.y = __uint_as_float(*reinterpret_cast<const unsigned int*>(&h1));
    *reinterpret_cast<float2*>(dst) = pk;
}

__device__ __forceinline__ void load4h(const __half2* src, float& x0, float& x1,
                                       float& x2, float& x3) {
    const float2 raw = *reinterpret_cast<const float2*>(src);
    const __half2 ha = *reinterpret_cast<const __half2*>(&raw.x);
    const __half2 hb = *reinterpret_cast<const __half2*>(&raw.y);
    const float2 fa = __half22float2(ha);
    const float2 fb = __half22float2(hb);
    x0 = fa.x; x1 = fa.y; x2 = fb.x; x3 = fb.y;
}

__global__ void __launch_bounds__(256, 3)
vae_fused_kernel(const float* __restrict__ rgb,  const float* __restrict__ pos,
                 const float* __restrict__ pos1, const float* __restrict__ pos2,
                 const int*   __restrict__ oi0,  const int* __restrict__ oi1,
                 const float* __restrict__ eps,
                 const float* __restrict__ W1l, const float* __restrict__ b1l,
                 const float* __restrict__ W1g, const float* __restrict__ b1g,
                 const float* __restrict__ W2l, const float* __restrict__ b2l,
                 const float* __restrict__ W2g, const float* __restrict__ b2g,
                 const float* __restrict__ W3l, const float* __restrict__ b3l,
                 const float* __restrict__ W3g, const float* __restrict__ b3g,
                 const float* __restrict__ Wlin, const float* __restrict__ blin,
                 float* __restrict__ out)
{
    extern __shared__ unsigned char smem_raw[];
    Smem& s = *reinterpret_cast<Smem*>(smem_raw);
    const int tid = threadIdx.x;
    const int gh  = tid >> 7;      // glimpse half for merged stages
    const int t   = tid & 127;
    const int g0  = blockIdx.x * 2;
    const int g   = g0 + gh;

    // ---------------- preamble ----------------------------------------------
    for (int i = tid; i < 64;  i += 256) s.w1l[i] = W1l[i];
    if (tid < 16) s.b1l[tid] = b1l[tid];
    if (tid < 32) s.b1g[tid] = b1g[tid];
    if (tid < 64) s.b2l[tid] = b2l[tid];
    for (int i = tid; i < 512; i += 256) s.w1g[i] = W1g[i];
    if (tid < 192) s.pos2l2[tid] = pos2[(size_t)g0 * 96 + tid];
    for (int i = t; i < 384; i += 128) s.pos1l[gh][i] = pos1[(size_t)g * 384 + i];
    s.cur[gh][t] = 0;
    if (t < 32) s.cur2[gh][t] = 0;
    __syncthreads();

    // ---------------- count phase (both glimpses) ---------------------------
    {
        const int c2 = (int)(oi1[(size_t)g * 128 + t] - g * CPG2);
        s.idx1[gh][t] = c2;
        atomicAdd(&s.cur2[gh][c2], 1);
    }
    for (int p = t; p < NPG; p += 128) {
        const size_t e = (size_t)g * NPG + p;
        float4 pt;
        pt.x = rgb[e];
        pt.y = pos[e * 3 + 0];
        pt.z = pos[e * 3 + 1];
        pt.w = pos[e * 3 + 2];
        s.B.pts[gh][p] = pt;
        atomicAdd(&s.cur[gh][oi0[e] - g * CPG], 1);
    }
    __syncthreads();

    // ---------------- prefix sums: 4 warps, one per (glimpse, level) --------
    {
        const int wid  = tid >> 5;
        const int lane = tid & 31;
        if (wid < 2) {
            const int gg = wid;
            int v0 = s.cur[gg][lane * 4 + 0], v1 = s.cur[gg][lane * 4 + 1];
            int v2 = s.cur[gg][lane * 4 + 2], v3 = s.cur[gg][lane * 4 + 3];
            int lsum = v0 + v1 + v2 + v3;
            int sc = lsum;
            #pragma unroll
            for (int off = 1; off < 32; off <<= 1) {
                int n = __shfl_up_sync(0xffffffffu, sc, off);
                if (lane >= off) sc += n;
            }
            int e0 = sc - lsum;
            int e1 = e0 + v0, e2 = e1 + v1, e3 = e2 + v2;
            s.ofs[gg][lane * 4 + 0] = (unsigned short)e0; s.cur[gg][lane * 4 + 0] = e0;
            s.ofs[gg][lane * 4 + 1] = (unsigned short)e1; s.cur[gg][lane * 4 + 1] = e1;
            s.ofs[gg][lane * 4 + 2] = (unsigned short)e2; s.cur[gg][lane * 4 + 2] = e2;
            s.ofs[gg][lane * 4 + 3] = (unsigned short)e3; s.cur[gg][lane * 4 + 3] = e3;
        } else if (wid < 4) {
            const int gg = wid - 2;
            int v = s.cur2[gg][lane];
            int sc = v;
            #pragma unroll
            for (int off = 1; off < 32; off <<= 1) {
                int n = __shfl_up_sync(0xffffffffu, sc, off);
                if (lane >= off) sc += n;
            }
            s.ofs2[gg][lane] = (unsigned short)(sc - v);
            s.cur2[gg][lane] = sc - v;
        }
    }
    __syncthreads();

    // ---------------- scatter passes (both glimpses) ------------------------
    for (int p = t; p < NPG; p += 128) {
        const int c = oi0[(size_t)g * NPG + p] - g * CPG;
        const int slot = atomicAdd(&s.cur[gh][c], 1);
        s.order[gh][slot] = (unsigned short)p;
    }
    {
        const int slot = atomicAdd(&s.cur2[gh][s.idx1[gh][t]], 1);
        s.order2[gh][slot] = (unsigned short)t;
    }
    __syncthreads();

    // ---------------- stage 1: gather edge MLP (4->16), both glimpses -------
    // 2 threads per cluster; each thread processes BOTH glimpses back-to-back
    // (independent work, no barrier between; stragglers average out).
    {
        const int c    = tid >> 1;
        const int half = tid & 1;
        float wb[8], w0r[8], w1r[8], w2r[8], w3r[8];
        #pragma unroll
        for (int j8 = 0; j8 < 8; j8++) {
            const int j = half * 8 + j8;
            wb[j8]  = s.b1l[j];
            w0r[j8] = s.w1l[j];
            w1r[j8] = s.w1l[16 + j];
            w2r[j8] = s.w1l[32 + j];
            w3r[j8] = s.w1l[48 + j];
        }
        #pragma unroll
        for (int gg = 0; gg < 2; gg++) {
            const int beg = (int)s.ofs[gg][c];
            const int n   = s.cur[gg][c] - beg;
            const float cx = s.pos1l[gg][c * 3 + 0];
            const float cy = s.pos1l[gg][c * 3 + 1];
            const float cz = s.pos1l[gg][c * 3 + 2];
            float acc[8];
            #pragma unroll
            for (int j8 = 0; j8 < 8; j8++) acc[j8] = 0.0f;
            for (int i = 0; i < n; i++) {
                const float4 pt = s.B.pts[gg][(int)s.order[gg][beg + i]];
                const float rx = pt.y - cx, ry = pt.z - cy, rz = pt.w - cz;
                #pragma unroll
                for (int j8 = 0; j8 < 8; j8++) {
                    float a = wb[j8];
                    a = fmaf(pt.x, w0r[j8], a);
                    a = fmaf(rx,   w1r[j8], a);
                    a = fmaf(ry,   w2r[j8], a);
                    a = fmaf(rz,   w3r[j8], a);
                    acc[j8] += celu1(a);
                }
            }
            const float inv = 1.0f / fmaxf((float)n, 1.0f);
            #pragma unroll
            for (int j8 = 0; j8 < 8; j8++)
                s.agg[gg][c * 16 + half * 8 + j8] = acc[j8] * inv;
        }
    }
    __syncthreads();

    // ---------------- stage 2: f1 = celu(mean1 @ W1g + b1g) -> fp16 ---------
    // merged: 128 threads per glimpse; 8 clusters per thread
    {
        const int jq = t & 7;
        const int cg = t >> 3;          // 16 groups x 8 clusters
        const float4* Wq = reinterpret_cast<const float4*>(s.w1g); // [16][8]
        float acc[8][4];
        #pragma unroll
        for (int c8 = 0; c8 < 8; c8++)
            #pragma unroll
            for (int u = 0; u < 4; u++) acc[c8][u] = s.b1g[jq * 4 + u];
        #pragma unroll
        for (int k = 0; k < 16; k++) {
            const float4 wv = Wq[k * 8 + jq];
            #pragma unroll
            for (int c8 = 0; c8 < 8; c8++) {
                const float x = s.agg[gh][(cg * 8 + c8) * 16 + k];
                FMA4(acc[c8], x, wv);
            }
        }
        #pragma unroll
        for (int c8 = 0; c8 < 8; c8++) {
            const int c = cg * 8 + c8;
            pack2h2(celu1(acc[c8][0]), celu1(acc[c8][1]),
                    celu1(acc[c8][2]), celu1(acc[c8][3]),
                    &s.A.f1h[gh][c * 16 + jq * 2]);
        }
    }
    __syncthreads();

    // ---------------- stage 3a: edge MLP (35->64) into h2 (fp16), FFMA2 -----
    // merged: 128 threads per glimpse; 16 edges per thread in 2 passes of 8
    {
        const int jq = t & 15;
        const int eg = t >> 4;          // 8 groups x 16 edges
        const ulonglong2* Wq = reinterpret_cast<const ulonglong2*>(W2l); // [35][16]q
        const float4 bb = reinterpret_cast<const float4*>(s.b2l)[jq];
        const u64t b01 = pack2(bb.x, bb.y), b23 = pack2(bb.z, bb.w);
        #pragma unroll
        for (int pass = 0; pass < 2; pass++) {
            const int ebase = eg * 16 + pass * 8;
            u64t acc[8][2];
            #pragma unroll
            for (int e = 0; e < 8; e++) { acc[e][0] = b01; acc[e][1] = b23; }
            #pragma unroll
            for (int kq = 0; kq < 8; kq++) {
                const ulonglong2 wa = Wq[(kq * 4 + 0) * 16 + jq];
                const ulonglong2 wb = Wq[(kq * 4 + 1) * 16 + jq];
                const ulonglong2 wc = Wq[(kq * 4 + 2) * 16 + jq];
                const ulonglong2 wd = Wq[(kq * 4 + 3) * 16 + jq];
                #pragma unroll
                for (int e = 0; e < 8; e++) {
                    float x0, x1, x2, x3;
                    load4h(&s.A.f1h[gh][(ebase + e) * 16 + kq * 2], x0, x1, x2, x3);
                    const u64t s0 = splat2(x0), s1 = splat2(x1);
                    const u64t s2 = splat2(x2), s3 = splat2(x3);
                    FMA2P(acc[e], s0, wa);
                    FMA2P(acc[e], s1, wb);
                    FMA2P(acc[e], s2, wc);
                    FMA2P(acc[e], s3, wd);
                }
            }
            #pragma unroll
            for (int k2 = 0; k2 < 3; k2++) {
                const ulonglong2 wv = Wq[(32 + k2) * 16 + jq];
                #pragma unroll
                for (int e = 0; e < 8; e++) {
                    const int ee = ebase + e;
                    const float r = s.pos1l[gh][ee * 3 + k2]
                                  - s.pos2l2[gh * 96 + s.idx1[gh][ee] * 3 + k2];
                    const u64t r2 = splat2(r);
                    FMA2P(acc[e], r2, wv);
                }
            }
            #pragma unroll
            for (int e = 0; e < 8; e++) {
                const int ee = ebase + e;
                float a0, a1, a2, a3;
                unpack2(acc[e][0], a0, a1);
                unpack2(acc[e][1], a2, a3);
                pack2h2(celu1(a0), celu1(a1), celu1(a2), celu1(a3),
                        &s.B.h2[gh][ee * 32 + jq * 2]);
            }
        }
    }
    __syncthreads();

    // ---------------- stage 3b: gather-reduce h2 -> mean2h, both glimpses ---
    // merged: 128 threads per glimpse; 4 threads per cluster, 16 features each
    {
        const int c2 = t >> 2;
        const int f4 = t & 3;
        const int beg = (int)s.ofs2[gh][c2];
        const int n   = s.cur2[gh][c2] - beg;
        float acc[16];
        #pragma unroll
        for (int k = 0; k < 16; k++) acc[k] = 0.0f;
        for (int i = 0; i < n; i++) {
            const int e = (int)s.order2[gh][beg + i];
            float x[16];
            load4h(&s.B.h2[gh][e * 32 + f4 * 8],     x[0],  x[1],  x[2],  x[3]);
            load4h(&s.B.h2[gh][e * 32 + f4 * 8 + 2], x[4],  x[5],  x[6],  x[7]);
            load4h(&s.B.h2[gh][e * 32 + f4 * 8 + 4], x[8],  x[9],  x[10], x[11]);
            load4h(&s.B.h2[gh][e * 32 + f4 * 8 + 6], x[12], x[13], x[14], x[15]);
            #pragma unroll
            for (int k = 0; k < 16; k++) acc[k] += x[k];
        }
        const float inv = 1.0f / fmaxf((float)n, 1.0f);
        #pragma unroll
        for (int q = 0; q < 4; q++)
            pack2h2(acc[q * 4 + 0] * inv, acc[q * 4 + 1] * inv,
                    acc[q * 4 + 2] * inv, acc[q * 4 + 3] * inv,
                    &s.mean2h[gh * 1024 + c2 * 32 + f4 * 8 + q * 2]);
    }
    __syncthreads();

    // ============ joint stages 4-7 ==========================================

    // stage 4: f2 = celu(mean2 @ W2g + b2g)  [2][32][128] -> fp16 — FFMA2
    {
        const int jq = tid & 31;
        const int cg = tid >> 5;
        const ulonglong2* Wq = reinterpret_cast<const ulonglong2*>(W2g); // [64][32]q
        const float4 bb = reinterpret_cast<const float4*>(b2g)[jq];
        const u64t b01 = pack2(bb.x, bb.y), b23 = pack2(bb.z, bb.w);
        u64t acc[2][4][2];
        #pragma unroll
        for (int gi = 0; gi < 2; gi++)
            #pragma unroll
            for (int c4 = 0; c4 < 4; c4++) { acc[gi][c4][0] = b01; acc[gi][c4][1] = b23; }
        #pragma unroll 2
        for (int kq = 0; kq < 16; kq++) {
            const ulonglong2 wa = Wq[(kq * 4 + 0) * 32 + jq];
            const ulonglong2 wb = Wq[(kq * 4 + 1) * 32 + jq];
            const ulonglong2 wc = Wq[(kq * 4 + 2) * 32 + jq];
            const ulonglong2 wd = Wq[(kq * 4 + 3) * 32 + jq];
            #pragma unroll
            for (int gi = 0; gi < 2; gi++)
                #pragma unroll
                for (int c4 = 0; c4 < 4; c4++) {
                    float x0, x1, x2, x3;
                    load4h(&s.mean2h[gi * 1024 + (cg * 4 + c4) * 32 + kq * 2],
                           x0, x1, x2, x3);
                    const u64t s0 = splat2(x0), s1 = splat2(x1);
                    const u64t s2 = splat2(x2), s3 = splat2(x3);
                    FMA2P(acc[gi][c4], s0, wa);
                    FMA2P(acc[gi][c4], s1, wb);
                    FMA2P(acc[gi][c4], s2, wc);
                    FMA2P(acc[gi][c4], s3, wd);
                }
        }
        #pragma unroll
        for (int gi = 0; gi < 2; gi++)
            #pragma unroll
            for (int c4 = 0; c4 < 4; c4++) {
                float a0, a1, a2, a3;
                unpack2(acc[gi][c4][0], a0, a1);
                unpack2(acc[gi][c4][1], a2, a3);
                pack2h2(celu1(a0), celu1(a1), celu1(a2), celu1(a3),
                        &s.B.f2h[(gi * 32 + cg * 4 + c4) * 64 + jq * 2]);
            }
    }
    __syncthreads();

    // stage 5: level-3 edge MLP (131 -> 128) + mean — FFMA2
    {
        const int jq = tid & 31;
        const int eg = tid >> 5;        // 8 groups x 4 edges
        const ulonglong2* Wq = reinterpret_cast<const ulonglong2*>(W3l); // [131][32]q
        const float4 bb = reinterpret_cast<const float4*>(b3l)[jq];
        const u64t b01 = pack2(bb.x, bb.y), b23 = pack2(bb.z, bb.w);
        u64t acc[2][4][2];
        #pragma unroll
        for (int gi = 0; gi < 2; gi++)
            #pragma unroll
            for (int e = 0; e < 4; e++) { acc[gi][e][0] = b01; acc[gi][e][1] = b23; }
        #pragma unroll 2
        for (int kq = 0; kq < 32; kq++) {
            const ulonglong2 wa = Wq[(kq * 4 + 0) * 32 + jq];
            const ulonglong2 wb = Wq[(kq * 4 + 1) * 32 + jq];
            const ulonglong2 wc = Wq[(kq * 4 + 2) * 32 + jq];
            const ulonglong2 wd = Wq[(kq * 4 + 3) * 32 + jq];
            #pragma unroll
            for (int gi = 0; gi < 2; gi++)
                #pragma unroll
                for (int e = 0; e < 4; e++) {
                    const int ee = eg * 4 + e;
                    float x0, x1, x2, x3;
                    load4h(&s.B.f2h[(gi * 32 + ee) * 64 + kq * 2], x0, x1, x2, x3);
                    const u64t s0 = splat2(x0), s1 = splat2(x1);
                    const u64t s2 = splat2(x2), s3 = splat2(x3);
                    FMA2P(acc[gi][e], s0, wa);
                    FMA2P(acc[gi][e], s1, wb);
                    FMA2P(acc[gi][e], s2, wc);
                    FMA2P(acc[gi][e], s3, wd);
                }
        }
        #pragma unroll
        for (int k2 = 0; k2 < 3; k2++) {
            const ulonglong2 wv = Wq[(128 + k2) * 32 + jq];
            #pragma unroll
            for (int gi = 0; gi < 2; gi++)
                #pragma unroll
                for (int e = 0; e < 4; e++) {
                    const float r = s.pos2l2[gi * 96 + (eg * 4 + e) * 3 + k2];
                    const u64t r2 = splat2(r);
                    FMA2P(acc[gi][e], r2, wv);
                }
        }
        #pragma unroll
        for (int gi = 0; gi < 2; gi++) {
            float a[4][4];
            #pragma unroll
            for (int e = 0; e < 4; e++) {
                unpack2(acc[gi][e][0], a[e][0], a[e][1]);
                unpack2(acc[gi][e][1], a[e][2], a[e][3]);
            }
            float4 pv;
            pv.x = celu1(a[0][0]) + celu1(a[1][0]) + celu1(a[2][0]) + celu1(a[3][0]);
            pv.y = celu1(a[0][1]) + celu1(a[1][1]) + celu1(a[2][1]) + celu1(a[3][1]);
            pv.z = celu1(a[0][2]) + celu1(a[1][2]) + celu1(a[2][2]) + celu1(a[3][2]);
            pv.w = celu1(a[0][3]) + celu1(a[1][3]) + celu1(a[2][3]) + celu1(a[3][3]);
            reinterpret_cast<float4*>(&s.A.psum[gi * 1024 + eg * 128 + jq * 4])[0] = pv;
        }
    }
    __syncthreads();
    {
        const int gi = tid >> 7;
        const int j  = tid & 127;
        float sum = 0.0f;
        #pragma unroll
        for (int e = 0; e < 8; e++) sum += s.A.psum[gi * 1024 + e * 128 + j];
        s.gsum[gi * 128 + j] = sum;
    }
    __syncthreads();

    // stage 6: f = celu((gsum/32) @ W3g + b3g), both glimpses
    {
        const int j = tid;
        float s0 = 0.0f, s1 = 0.0f;
        #pragma unroll 8
        for (int k = 0; k < 128; k++) {
            const float w = W3g[k * 256 + j];
            s0 = fmaf(s.gsum[k],       w, s0);
            s1 = fmaf(s.gsum[128 + k], w, s1);
        }
        const float bj = b3g[j];
        const float f0 = celu1(fmaf(s0, 0.03125f, bj));
        const float f1 = celu1(fmaf(s1, 0.03125f, bj));
        s.fvec[j] = f0;
        s.fvec[256 + j] = f1;
        out[OFF_F + (size_t)g0 * 256 + j] = f0;
        out[OFF_F + (size_t)(g0 + 1) * 256 + j] = f1;
    }
    __syncthreads();

    // stage 7: out = f @ Wlin + blin, both glimpses
    {
        const int j = tid;
        const float bj = blin[j];
        float a0 = bj, a1 = bj;
        #pragma unroll 8
        for (int k = 0; k < 256; k++) {
            const float w = Wlin[k * 256 + j];
            a0 = fmaf(s.fvec[k],       w, a0);
            a1 = fmaf(s.fvec[256 + k], w, a1);
        }
        s.outv[j] = a0;
        s.outv[256 + j] = a1;
    }
    __syncthreads();

    if (tid < 128) {
        #pragma unroll
        for (int gi = 0; gi < 2; gi++) {
            const size_t gg = g0 + gi;
            const float mu = s.outv[gi * 256 + tid];
            const float sg = s.outv[gi * 256 + 128 + tid];
            const float sigma = fmaxf(sg, 0.0f) + log1pf(__expf(-fabsf(sg)));
            const float z = fmaf(sigma, eps[gg * 128 + tid], mu);
            out[OFF_MU    + gg * 128 + tid] = mu;
            out[OFF_SIGMA + gg * 128 + tid] = sigma;
            if (tid < 64) out[OFF_ZWHAT + gg * 64 + tid] = z;
            else          out[OFF_ZMASK + gg * 64 + (tid - 64)] = z;
        }
    }
}

extern "C" void kernel_launch(void* const* d_in, const int* in_sizes, int n_in,
                              void* d_out, int out_size)
{
    const float* rgb  = (const float*)d_in[0];
    const float* pos  = (const float*)d_in[1];
    const float* pos1 = (const float*)d_in[2];
    const float* pos2 = (const float*)d_in[3];
    const int*   oi0  = (const int*)  d_in[4];
    const int*   oi1  = (const int*)  d_in[5];
    const float* eps  = (const float*)d_in[7];
    const float* W1l  = (const float*)d_in[8];
    const float* b1l  = (const float*)d_in[9];
    const float* W1g  = (const float*)d_in[10];
    const float* b1g  = (const float*)d_in[11];
    const float* W2l  = (const float*)d_in[12];
    const float* b2l  = (const float*)d_in[13];
    const float* W2g  = (const float*)d_in[14];
    const float* b2g  = (const float*)d_in[15];
    const float* W3l  = (const float*)d_in[16];
    const float* b3l  = (const float*)d_in[17];
    const float* W3g  = (const float*)d_in[18];
    const float* b3g  = (const float*)d_in[19];
    const float* Wlin = (const float*)d_in[20];
    const float* blin = (const float*)d_in[21];
    float* out = (float*)d_out;

    cudaFuncSetAttribute(vae_fused_kernel,
                         cudaFuncAttributeMaxDynamicSharedMemorySize,
                         (int)sizeof(Smem));
    vae_fused_kernel<<<NG / 2, 256, sizeof(Smem)>>>(
        rgb, pos, pos1, pos2, oi0, oi1, eps,
        W1l, b1l, W1g, b1g, W2l, b2l, W2g, b2g,
        W3l, b3l, W3g, b3g, Wlin, blin, out);
}

// round 13
// speedup vs baseline: 1.9836x; 1.9836x over previous
#include <cuda_runtime.h>
#include <cuda_fp16.h>
#include <math.h>

// Problem constants
#define NG    2048
#define NPG   512
#define CPG   128
#define CPG2  32

// Output layout (float32)
#define OFF_ZWHAT 0
#define OFF_ZMASK 131072
#define OFF_MU    262144
#define OFF_SIGMA 524288
#define OFF_F     786432

struct __align__(16) Smem {
    float w1l[64];      // [4][16]
    float b1l[16];
    float b1g[32];
    float b2l[64];
    float w1g[512];     // [16][32]
    float pos1l[2][384];    // both glimpses
    float pos2l2[192];      // [2][32][3]
    int   idx1[2][128];
    int   cur[2][128];
    int   cur2[2][32];
    unsigned short ofs[2][128];
    unsigned short ofs2[2][32];
    unsigned short order[2][512];
    unsigned short order2[2][128];
    float agg[2048];        // stage1 mean [128][16] (per-glimpse reuse)
    __half2 mean2h[2048];   // [2][32][32h2]
    float gsum[256];
    float fvec[512];
    float outv[512];
    union {                 // 8 KB (single-instance, per-glimpse reuse)
        __half2 f1h[2048];  // [128][16h2]
        float   psum[2048]; // [2][8][128]
    } A;
    union {                 // 16 KB (single-instance, per-glimpse reuse)
        float4  pts[512];
        __half2 h2[4096];   // [128][32h2]
        __half2 f2h[4096];  // [2][32][64h2]
    } B;
};

typedef unsigned long long u64t;

__device__ __forceinline__ float celu1(float x) {
    return fmaxf(x, 0.0f) + (__expf(fminf(x, 0.0f)) - 1.0f);
}

// ---- packed fp32x2 helpers (Blackwell FFMA2) ----
__device__ __forceinline__ u64t splat2(float x) {
    u64t r; asm("mov.b64 %0, {%1, %1};" : "=l"(r) : "f"(x)); return r;
}
__device__ __forceinline__ u64t pack2(float lo, float hi) {
    u64t r; asm("mov.b64 %0, {%1, %2};" : "=l"(r) : "f"(lo), "f"(hi)); return r;
}
__device__ __forceinline__ void unpack2(u64t v, float& lo, float& hi) {
    asm("mov.b64 {%0, %1}, %2;" : "=f"(lo), "=f"(hi) : "l"(v));
}
__device__ __forceinline__ void ffma2(u64t& acc, u64t a, u64t b) {
    asm("fma.rn.f32x2 %0, %1, %2, %0;" : "+l"(acc) : "l"(a), "l"(b));
}
#define FMA2P(accp, xs2, wv2) \
    { ffma2((accp)[0], (xs2), (wv2).x); ffma2((accp)[1], (xs2), (wv2).y); }

#define FMA4(Aacc, xs, wv) \
    { Aacc[0] = fmaf((xs), (wv).x, Aacc[0]); Aacc[1] = fmaf((xs), (wv).y, Aacc[1]); \
      Aacc[2] = fmaf((xs), (wv).z, Aacc[2]); Aacc[3] = fmaf((xs), (wv).w, Aacc[3]); }

__device__ __forceinline__ void pack2h2(float a0, float a1, float a2, float a3,
                                        __half2* dst) {
    const __half2 h0 = __floats2half2_rn(a0, a1);
    const __half2 h1 = __floats2half2_rn(a2, a3);
    float2 pk;
    pk.x = __uint_as_float(*reinterpret_cast<const unsigned int*>(&h0));
    pk.y = __uint_as_float(*reinterpret_cast<const unsigned int*>(&h1));
    *reinterpret_cast<float2*>(dst) = pk;
}

__device__ __forceinline__ void load4h(const __half2* src, float& x0, float& x1,
                                       float& x2, float& x3) {
    const float2 raw = *reinterpret_cast<const float2*>(src);
    const __half2 ha = *reinterpret_cast<const __half2*>(&raw.x);
    const __half2 hb = *reinterpret_cast<const __half2*>(&raw.y);
    const float2 fa = __half22float2(ha);
    const float2 fb = __half22float2(hb);
    x0 = fa.x; x1 = fa.y; x2 = fb.x; x3 = fb.y;
}

__global__ void __launch_bounds__(256, 3)
vae_fused_kernel(const float* __restrict__ rgb,  const float* __restrict__ pos,
                 const float* __restrict__ pos1, const float* __restrict__ pos2,
                 const int*   __restrict__ oi0,  const int* __restrict__ oi1,
                 const float* __restrict__ eps,
                 const float* __restrict__ W1l, const float* __restrict__ b1l,
                 const float* __restrict__ W1g, const float* __restrict__ b1g,
                 const float* __restrict__ W2l, const float* __restrict__ b2l,
                 const float* __restrict__ W2g, const float* __restrict__ b2g,
                 const float* __restrict__ W3l, const float* __restrict__ b3l,
                 const float* __restrict__ W3g, const float* __restrict__ b3g,
                 const float* __restrict__ Wlin, const float* __restrict__ blin,
                 float* __restrict__ out)
{
    extern __shared__ unsigned char smem_raw[];
    Smem& s = *reinterpret_cast<Smem*>(smem_raw);
    const int tid = threadIdx.x;
    const int g0  = blockIdx.x * 2;

    // ---------------- preamble: weights + both glimpses' geometry -----------
    for (int i = tid; i < 64;  i += 256) s.w1l[i] = W1l[i];
    if (tid < 16) s.b1l[tid] = b1l[tid];
    if (tid < 32) s.b1g[tid] = b1g[tid];
    if (tid < 64) s.b2l[tid] = b2l[tid];
    for (int i = tid; i < 512; i += 256) s.w1g[i] = W1g[i];
    if (tid < 192) s.pos2l2[tid] = pos2[(size_t)g0 * 96 + tid];
    // load pos1 for both glimpses (768 floats); each index written by ONE thread
    for (int i = tid; i < 768; i += 256) {
        const int gg = i / 384;
        s.pos1l[gg][i - gg * 384] = pos1[(size_t)(g0 + gg) * 384 + (i - gg * 384)];
    }
    if (tid < 128) { s.cur[0][tid] = 0; s.cur[1][tid] = 0; }
    if (tid < 32)  { s.cur2[0][tid] = 0; s.cur2[1][tid] = 0; }
    __syncthreads();

    // ---------------- metadata: count both glimpses, stage g0 pts -----------
    {
        const int gh = tid >> 7;
        const int t  = tid & 127;
        const int gg = g0 + gh;
        const int c2 = (int)(oi1[(size_t)gg * 128 + t] - gg * CPG2);
        s.idx1[gh][t] = c2;
        atomicAdd(&s.cur2[gh][c2], 1);
    }
    for (int p = tid; p < NPG; p += 256) {
        const size_t e = (size_t)g0 * NPG + p;
        float4 pt;
        pt.x = rgb[e];
        pt.y = pos[e * 3 + 0];
        pt.z = pos[e * 3 + 1];
        pt.w = pos[e * 3 + 2];
        s.B.pts[p] = pt;
        atomicAdd(&s.cur[0][oi0[e] - g0 * CPG], 1);
    }
    for (int p = tid; p < NPG; p += 256) {
        const size_t e = (size_t)(g0 + 1) * NPG + p;
        atomicAdd(&s.cur[1][oi0[e] - (g0 + 1) * CPG], 1);
    }
    __syncthreads();

    // ---------------- prefix sums: 4 warps, one per (glimpse, level) --------
    {
        const int wid  = tid >> 5;
        const int lane = tid & 31;
        if (wid < 2) {
            const int gg = wid;
            int v0 = s.cur[gg][lane * 4 + 0], v1 = s.cur[gg][lane * 4 + 1];
            int v2 = s.cur[gg][lane * 4 + 2], v3 = s.cur[gg][lane * 4 + 3];
            int lsum = v0 + v1 + v2 + v3;
            int sc = lsum;
            #pragma unroll
            for (int off = 1; off < 32; off <<= 1) {
                int n = __shfl_up_sync(0xffffffffu, sc, off);
                if (lane >= off) sc += n;
            }
            int e0 = sc - lsum;
            int e1 = e0 + v0, e2 = e1 + v1, e3 = e2 + v2;
            s.ofs[gg][lane * 4 + 0] = (unsigned short)e0; s.cur[gg][lane * 4 + 0] = e0;
            s.ofs[gg][lane * 4 + 1] = (unsigned short)e1; s.cur[gg][lane * 4 + 1] = e1;
            s.ofs[gg][lane * 4 + 2] = (unsigned short)e2; s.cur[gg][lane * 4 + 2] = e2;
            s.ofs[gg][lane * 4 + 3] = (unsigned short)e3; s.cur[gg][lane * 4 + 3] = e3;
        } else if (wid < 4) {
            const int gg = wid - 2;
            int v = s.cur2[gg][lane];
            int sc = v;
            #pragma unroll
            for (int off = 1; off < 32; off <<= 1) {
                int n = __shfl_up_sync(0xffffffffu, sc, off);
                if (lane >= off) sc += n;
            }
            s.ofs2[gg][lane] = (unsigned short)(sc - v);
            s.cur2[gg][lane] = sc - v;
        }
    }
    __syncthreads();

    // ---------------- scatter: both glimpses, both levels -------------------
    for (int p = tid; p < NPG; p += 256) {
        const int c = oi0[(size_t)g0 * NPG + p] - g0 * CPG;
        const int slot = atomicAdd(&s.cur[0][c], 1);
        s.order[0][slot] = (unsigned short)p;
    }
    for (int p = tid; p < NPG; p += 256) {
        const int c = oi0[(size_t)(g0 + 1) * NPG + p] - (g0 + 1) * CPG;
        const int slot = atomicAdd(&s.cur[1][c], 1);
        s.order[1][slot] = (unsigned short)p;
    }
    {
        const int gh = tid >> 7;
        const int t  = tid & 127;
        const int slot = atomicAdd(&s.cur2[gh][s.idx1[gh][t]], 1);
        s.order2[gh][slot] = (unsigned short)t;
    }
    __syncthreads();

    // ============ per-glimpse compute stages 1-3 ============================
    for (int gi = 0; gi < 2; gi++) {
        if (gi == 1) {
            // stage glimpse-1 points (h2 of glimpse 0 fully consumed)
            for (int p = tid; p < NPG; p += 256) {
                const size_t e = (size_t)(g0 + 1) * NPG + p;
                float4 pt;
                pt.x = rgb[e];
                pt.y = pos[e * 3 + 0];
                pt.z = pos[e * 3 + 1];
                pt.w = pos[e * 3 + 2];
                s.B.pts[p] = pt;
            }
            __syncthreads();
        }

        // stage 1: gather edge MLP (4 -> 16) + mean
        {
            const int c    = tid >> 1;
            const int half = tid & 1;
            const int beg = (int)s.ofs[gi][c];
            const int n   = s.cur[gi][c] - beg;
            const float cx = s.pos1l[gi][c * 3 + 0];
            const float cy = s.pos1l[gi][c * 3 + 1];
            const float cz = s.pos1l[gi][c * 3 + 2];
            float wb[8], w0r[8], w1r[8], w2r[8], w3r[8];
            #pragma unroll
            for (int j8 = 0; j8 < 8; j8++) {
                const int j = half * 8 + j8;
                wb[j8]  = s.b1l[j];
                w0r[j8] = s.w1l[j];
                w1r[j8] = s.w1l[16 + j];
                w2r[j8] = s.w1l[32 + j];
                w3r[j8] = s.w1l[48 + j];
            }
            float acc[8];
            #pragma unroll
            for (int j8 = 0; j8 < 8; j8++) acc[j8] = 0.0f;
            for (int i = 0; i < n; i++) {
                const float4 pt = s.B.pts[(int)s.order[gi][beg + i]];
                const float rx = pt.y - cx, ry = pt.z - cy, rz = pt.w - cz;
                #pragma unroll
                for (int j8 = 0; j8 < 8; j8++) {
                    float a = wb[j8];
                    a = fmaf(pt.x, w0r[j8], a);
                    a = fmaf(rx,   w1r[j8], a);
                    a = fmaf(ry,   w2r[j8], a);
                    a = fmaf(rz,   w3r[j8], a);
                    acc[j8] += celu1(a);
                }
            }
            const float inv = 1.0f / fmaxf((float)n, 1.0f);
            #pragma unroll
            for (int j8 = 0; j8 < 8; j8++)
                s.agg[c * 16 + half * 8 + j8] = acc[j8] * inv;
        }
        __syncthreads();

        // stage 2: f1 = celu(mean1 @ W1g + b1g)  [128][32] -> fp16
        {
            const int jq = tid & 7;
            const int cg = tid >> 3;
            const float4* Wq = reinterpret_cast<const float4*>(s.w1g); // [16][8]
            float acc[4][4];
            #pragma unroll
            for (int c4 = 0; c4 < 4; c4++)
                #pragma unroll
                for (int u = 0; u < 4; u++) acc[c4][u] = s.b1g[jq * 4 + u];
            #pragma unroll
            for (int k = 0; k < 16; k++) {
                const float4 wv = Wq[k * 8 + jq];
                #pragma unroll
                for (int c4 = 0; c4 < 4; c4++) {
                    const float x = s.agg[(cg * 4 + c4) * 16 + k];
                    FMA4(acc[c4], x, wv);
                }
            }
            #pragma unroll
            for (int c4 = 0; c4 < 4; c4++) {
                const int c = cg * 4 + c4;
                pack2h2(celu1(acc[c4][0]), celu1(acc[c4][1]),
                        celu1(acc[c4][2]), celu1(acc[c4][3]),
                        &s.A.f1h[c * 16 + jq * 2]);
            }
        }
        __syncthreads();

        // stage 3a: edge MLP (35 -> 64) into h2 (fp16) — FFMA2
        {
            const int jq = tid & 15;
            const int eg = tid >> 4;
            const ulonglong2* Wq = reinterpret_cast<const ulonglong2*>(W2l); // [35][16]q
            const float4 bb = reinterpret_cast<const float4*>(s.b2l)[jq];
            const u64t b01 = pack2(bb.x, bb.y), b23 = pack2(bb.z, bb.w);
            u64t acc[8][2];
            #pragma unroll
            for (int e = 0; e < 8; e++) { acc[e][0] = b01; acc[e][1] = b23; }
            #pragma unroll
            for (int kq = 0; kq < 8; kq++) {
                const ulonglong2 wa = Wq[(kq * 4 + 0) * 16 + jq];
                const ulonglong2 wb = Wq[(kq * 4 + 1) * 16 + jq];
                const ulonglong2 wc = Wq[(kq * 4 + 2) * 16 + jq];
                const ulonglong2 wd = Wq[(kq * 4 + 3) * 16 + jq];
                #pragma unroll
                for (int e = 0; e < 8; e++) {
                    float x0, x1, x2, x3;
                    load4h(&s.A.f1h[(eg * 8 + e) * 16 + kq * 2], x0, x1, x2, x3);
                    const u64t s0 = splat2(x0), s1 = splat2(x1);
                    const u64t s2 = splat2(x2), s3 = splat2(x3);
                    FMA2P(acc[e], s0, wa);
                    FMA2P(acc[e], s1, wb);
                    FMA2P(acc[e], s2, wc);
                    FMA2P(acc[e], s3, wd);
                }
            }
            #pragma unroll
            for (int k2 = 0; k2 < 3; k2++) {
                const ulonglong2 wv = Wq[(32 + k2) * 16 + jq];
                #pragma unroll
                for (int e = 0; e < 8; e++) {
                    const int ee = eg * 8 + e;
                    const float r = s.pos1l[gi][ee * 3 + k2]
                                  - s.pos2l2[gi * 96 + s.idx1[gi][ee] * 3 + k2];
                    const u64t r2 = splat2(r);
                    FMA2P(acc[e], r2, wv);
                }
            }
            #pragma unroll
            for (int e = 0; e < 8; e++) {
                const int ee = eg * 8 + e;
                float a0, a1, a2, a3;
                unpack2(acc[e][0], a0, a1);
                unpack2(acc[e][1], a2, a3);
                pack2h2(celu1(a0), celu1(a1), celu1(a2), celu1(a3),
                        &s.B.h2[ee * 32 + jq * 2]);
            }
        }
        __syncthreads();

        // stage 3b: gather-reduce h2 -> mean2h[gi] [32][64] fp16
        {
            const int c2 = tid >> 3;
            const int f8 = tid & 7;
            const int beg = (int)s.ofs2[gi][c2];
            const int n   = s.cur2[gi][c2] - beg;
            float acc[8];
            #pragma unroll
            for (int k = 0; k < 8; k++) acc[k] = 0.0f;
            for (int i = 0; i < n; i++) {
                const int e = (int)s.order2[gi][beg + i];
                float x0, x1, x2, x3, x4, x5, x6, x7;
                load4h(&s.B.h2[e * 32 + f8 * 4],     x0, x1, x2, x3);
                load4h(&s.B.h2[e * 32 + f8 * 4 + 2], x4, x5, x6, x7);
                acc[0] += x0; acc[1] += x1; acc[2] += x2; acc[3] += x3;
                acc[4] += x4; acc[5] += x5; acc[6] += x6; acc[7] += x7;
            }
            const float inv = 1.0f / fmaxf((float)n, 1.0f);
            pack2h2(acc[0] * inv, acc[1] * inv, acc[2] * inv, acc[3] * inv,
                    &s.mean2h[gi * 1024 + c2 * 32 + f8 * 4]);
            pack2h2(acc[4] * inv, acc[5] * inv, acc[6] * inv, acc[7] * inv,
                    &s.mean2h[gi * 1024 + c2 * 32 + f8 * 4 + 2]);
        }
        __syncthreads();
    }

    // ============ joint stages 4-7 ==========================================

    // stage 4: f2 = celu(mean2 @ W2g + b2g)  [2][32][128] -> fp16 — FFMA2
    {
        const int jq = tid & 31;
        const int cg = tid >> 5;
        const ulonglong2* Wq = reinterpret_cast<const ulonglong2*>(W2g); // [64][32]q
        const float4 bb = reinterpret_cast<const float4*>(b2g)[jq];
        const u64t b01 = pack2(bb.x, bb.y), b23 = pack2(bb.z, bb.w);
        u64t acc[2][4][2];
        #pragma unroll
        for (int gi = 0; gi < 2; gi++)
            #pragma unroll
            for (int c4 = 0; c4 < 4; c4++) { acc[gi][c4][0] = b01; acc[gi][c4][1] = b23; }
        #pragma unroll 2
        for (int kq = 0; kq < 16; kq++) {
            const ulonglong2 wa = Wq[(kq * 4 + 0) * 32 + jq];
            const ulonglong2 wb = Wq[(kq * 4 + 1) * 32 + jq];
            const ulonglong2 wc = Wq[(kq * 4 + 2) * 32 + jq];
            const ulonglong2 wd = Wq[(kq * 4 + 3) * 32 + jq];
            #pragma unroll
            for (int gi = 0; gi < 2; gi++)
                #pragma unroll
                for (int c4 = 0; c4 < 4; c4++) {
                    float x0, x1, x2, x3;
                    load4h(&s.mean2h[gi * 1024 + (cg * 4 + c4) * 32 + kq * 2],
                           x0, x1, x2, x3);
                    const u64t s0 = splat2(x0), s1 = splat2(x1);
                    const u64t s2 = splat2(x2), s3 = splat2(x3);
                    FMA2P(acc[gi][c4], s0, wa);
                    FMA2P(acc[gi][c4], s1, wb);
                    FMA2P(acc[gi][c4], s2, wc);
                    FMA2P(acc[gi][c4], s3, wd);
                }
        }
        #pragma unroll
        for (int gi = 0; gi < 2; gi++)
            #pragma unroll
            for (int c4 = 0; c4 < 4; c4++) {
                float a0, a1, a2, a3;
                unpack2(acc[gi][c4][0], a0, a1);
                unpack2(acc[gi][c4][1], a2, a3);
                pack2h2(celu1(a0), celu1(a1), celu1(a2), celu1(a3),
                        &s.B.f2h[(gi * 32 + cg * 4 + c4) * 64 + jq * 2]);
            }
    }
    __syncthreads();

    // stage 5: level-3 edge MLP (131 -> 128) + mean — FFMA2
    {
        const int jq = tid & 31;
        const int eg = tid >> 5;        // 8 groups x 4 edges
        const ulonglong2* Wq = reinterpret_cast<const ulonglong2*>(W3l); // [131][32]q
        const float4 bb = reinterpret_cast<const float4*>(b3l)[jq];
        const u64t b01 = pack2(bb.x, bb.y), b23 = pack2(bb.z, bb.w);
        u64t acc[2][4][2];
        #pragma unroll
        for (int gi = 0; gi < 2; gi++)
            #pragma unroll
            for (int e = 0; e < 4; e++) { acc[gi][e][0] = b01; acc[gi][e][1] = b23; }
        #pragma unroll 2
        for (int kq = 0; kq < 32; kq++) {
            const ulonglong2 wa = Wq[(kq * 4 + 0) * 32 + jq];
            const ulonglong2 wb = Wq[(kq * 4 + 1) * 32 + jq];
            const ulonglong2 wc = Wq[(kq * 4 + 2) * 32 + jq];
            const ulonglong2 wd = Wq[(kq * 4 + 3) * 32 + jq];
            #pragma unroll
            for (int gi = 0; gi < 2; gi++)
                #pragma unroll
                for (int e = 0; e < 4; e++) {
                    const int ee = eg * 4 + e;
                    float x0, x1, x2, x3;
                    load4h(&s.B.f2h[(gi * 32 + ee) * 64 + kq * 2], x0, x1, x2, x3);
                    const u64t s0 = splat2(x0), s1 = splat2(x1);
                    const u64t s2 = splat2(x2), s3 = splat2(x3);
                    FMA2P(acc[gi][e], s0, wa);
                    FMA2P(acc[gi][e], s1, wb);
                    FMA2P(acc[gi][e], s2, wc);
                    FMA2P(acc[gi][e], s3, wd);
                }
        }
        #pragma unroll
        for (int k2 = 0; k2 < 3; k2++) {
            const ulonglong2 wv = Wq[(128 + k2) * 32 + jq];
            #pragma unroll
            for (int gi = 0; gi < 2; gi++)
                #pragma unroll
                for (int e = 0; e < 4; e++) {
                    const float r = s.pos2l2[gi * 96 + (eg * 4 + e) * 3 + k2];
                    const u64t r2 = splat2(r);
                    FMA2P(acc[gi][e], r2, wv);
                }
        }
        #pragma unroll
        for (int gi = 0; gi < 2; gi++) {
            float a[4][4];
            #pragma unroll
            for (int e = 0; e < 4; e++) {
                unpack2(acc[gi][e][0], a[e][0], a[e][1]);
                unpack2(acc[gi][e][1], a[e][2], a[e][3]);
            }
            float4 pv;
            pv.x = celu1(a[0][0]) + celu1(a[1][0]) + celu1(a[2][0]) + celu1(a[3][0]);
            pv.y = celu1(a[0][1]) + celu1(a[1][1]) + celu1(a[2][1]) + celu1(a[3][1]);
            pv.z = celu1(a[0][2]) + celu1(a[1][2]) + celu1(a[2][2]) + celu1(a[3][2]);
            pv.w = celu1(a[0][3]) + celu1(a[1][3]) + celu1(a[2][3]) + celu1(a[3][3]);
            reinterpret_cast<float4*>(&s.A.psum[gi * 1024 + eg * 128 + jq * 4])[0] = pv;
        }
    }
    __syncthreads();
    {
        const int gi = tid >> 7;
        const int j  = tid & 127;
        float sum = 0.0f;
        #pragma unroll
        for (int e = 0; e < 8; e++) sum += s.A.psum[gi * 1024 + e * 128 + j];
        s.gsum[gi * 128 + j] = sum;
    }
    __syncthreads();

    // stage 6: f = celu((gsum/32) @ W3g + b3g), both glimpses
    {
        const int j = tid;
        float s0 = 0.0f, s1 = 0.0f;
        #pragma unroll 8
        for (int k = 0; k < 128; k++) {
            const float w = W3g[k * 256 + j];
            s0 = fmaf(s.gsum[k],       w, s0);
            s1 = fmaf(s.gsum[128 + k], w, s1);
        }
        const float bj = b3g[j];
        const float f0 = celu1(fmaf(s0, 0.03125f, bj));
        const float f1 = celu1(fmaf(s1, 0.03125f, bj));
        s.fvec[j] = f0;
        s.fvec[256 + j] = f1;
        out[OFF_F + (size_t)g0 * 256 + j] = f0;
        out[OFF_F + (size_t)(g0 + 1) * 256 + j] = f1;
    }
    __syncthreads();

    // stage 7: out = f @ Wlin + blin, both glimpses
    {
        const int j = tid;
        const float bj = blin[j];
        float a0 = bj, a1 = bj;
        #pragma unroll 8
        for (int k = 0; k < 256; k++) {
            const float w = Wlin[k * 256 + j];
            a0 = fmaf(s.fvec[k],       w, a0);
            a1 = fmaf(s.fvec[256 + k], w, a1);
        }
        s.outv[j] = a0;
        s.outv[256 + j] = a1;
    }
    __syncthreads();

    if (tid < 128) {
        #pragma unroll
        for (int gi = 0; gi < 2; gi++) {
            const size_t g = g0 + gi;
            const float mu = s.outv[gi * 256 + tid];
            const float sg = s.outv[gi * 256 + 128 + tid];
            const float sigma = fmaxf(sg, 0.0f) + log1pf(__expf(-fabsf(sg)));
            const float z = fmaf(sigma, eps[g * 128 + tid], mu);
            out[OFF_MU    + g * 128 + tid] = mu;
            out[OFF_SIGMA + g * 128 + tid] = sigma;
            if (tid < 64) out[OFF_ZWHAT + g * 64 + tid] = z;
            else          out[OFF_ZMASK + g * 64 + (tid - 64)] = z;
        }
    }
}

extern "C" void kernel_launch(void* const* d_in, const int* in_sizes, int n_in,
                              void* d_out, int out_size)
{
    const float* rgb  = (const float*)d_in[0];
    const float* pos  = (const float*)d_in[1];
    const float* pos1 = (const float*)d_in[2];
    const float* pos2 = (const float*)d_in[3];
    const int*   oi0  = (const int*)  d_in[4];
    const int*   oi1  = (const int*)  d_in[5];
    const float* eps  = (const float*)d_in[7];
    const float* W1l  = (const float*)d_in[8];
    const float* b1l  = (const float*)d_in[9];
    const float* W1g  = (const float*)d_in[10];
    const float* b1g  = (const float*)d_in[11];
    const float* W2l  = (const float*)d_in[12];
    const float* b2l  = (const float*)d_in[13];
    const float* W2g  = (const float*)d_in[14];
    const float* b2g  = (const float*)d_in[15];
    const float* W3l  = (const float*)d_in[16];
    const float* b3l  = (const float*)d_in[17];
    const float* W3g  = (const float*)d_in[18];
    const float* b3g  = (const float*)d_in[19];
    const float* Wlin = (const float*)d_in[20];
    const float* blin = (const float*)d_in[21];
    float* out = (float*)d_out;

    cudaFuncSetAttribute(vae_fused_kernel,
                         cudaFuncAttributeMaxDynamicSharedMemorySize,
                         (int)sizeof(Smem));
    vae_fused_kernel<<<NG / 2, 256, sizeof(Smem)>>>(
        rgb, pos, pos1, pos2, oi0, oi1, eps,
        W1l, b1l, W1g, b1g, W2l, b2l, W2g, b2g,
        W3l, b3l, W3g, b3g, Wlin, blin, out);
}

// round 14
// speedup vs baseline: 2.1084x; 1.0629x over previous
#include <cuda_runtime.h>
#include <cuda_fp16.h>
#include <math.h>

// Problem constants
#define NG    2048
#define NPG   512
#define CPG   128
#define CPG2  32

// Output layout (float32)
#define OFF_ZWHAT 0
#define OFF_ZMASK 131072
#define OFF_MU    262144
#define OFF_SIGMA 524288
#define OFF_F     786432

// fp16 transposed copy of W3l[0:128][0:128]: g_W3lT[n][k]
__device__ __half g_W3lT[128 * 128];

struct __align__(16) Smem {
    float w1l[64];      // [4][16]
    float b1l[16];
    float b1g[32];
    float b2l[64];
    float w1g[512];     // [16][32]
    float pos1l[384];   // [128][3]      (per-glimpse, reloaded)
    float pos2l2[192];  // [2][32][3]    (both glimpses)
    int   idx1[128];
    int   cur[128];
    int   cur2[32];
    unsigned short ofs[128];
    unsigned short ofs2[32];
    unsigned short order[512];
    unsigned short order2[128];
    float agg[2048];        // stage1 mean [128][16] (per-glimpse reuse)
    __half2 mean2h[2048];   // [2][32][32h2]
    float gsum[256];
    float fvec[512];
    float outv[512];
    union {                 // 8 KB (single-instance, per-glimpse reuse)
        __half2 f1h[2048];  // [128][16h2]
    } A;
    union {                 // 16 KB (single-instance, per-glimpse reuse)
        float4  pts[512];
        __half2 h2[4096];   // [128][32h2]
        __half2 f2h[4096];  // [2][32][64h2] joint stage4->5 (A operand for mma)
        float   psum2[4096];// [16 slots][256] stage-5 partial sums
    } B;
};

typedef unsigned long long u64t;

__device__ __forceinline__ float celu1(float x) {
    return fmaxf(x, 0.0f) + (__expf(fminf(x, 0.0f)) - 1.0f);
}

// ---- packed fp32x2 helpers (Blackwell FFMA2) ----
__device__ __forceinline__ u64t splat2(float x) {
    u64t r; asm("mov.b64 %0, {%1, %1};" : "=l"(r) : "f"(x)); return r;
}
__device__ __forceinline__ u64t pack2(float lo, float hi) {
    u64t r; asm("mov.b64 %0, {%1, %2};" : "=l"(r) : "f"(lo), "f"(hi)); return r;
}
__device__ __forceinline__ void unpack2(u64t v, float& lo, float& hi) {
    asm("mov.b64 {%0, %1}, %2;" : "=f"(lo), "=f"(hi) : "l"(v));
}
__device__ __forceinline__ void ffma2(u64t& acc, u64t a, u64t b) {
    asm("fma.rn.f32x2 %0, %1, %2, %0;" : "+l"(acc) : "l"(a), "l"(b));
}
#define FMA2P(accp, xs2, wv2) \
    { ffma2((accp)[0], (xs2), (wv2).x); ffma2((accp)[1], (xs2), (wv2).y); }

#define FMA4(Aacc, xs, wv) \
    { Aacc[0] = fmaf((xs), (wv).x, Aacc[0]); Aacc[1] = fmaf((xs), (wv).y, Aacc[1]); \
      Aacc[2] = fmaf((xs), (wv).z, Aacc[2]); Aacc[3] = fmaf((xs), (wv).w, Aacc[3]); }

__device__ __forceinline__ void pack2h2(float a0, float a1, float a2, float a3,
                                        __half2* dst) {
    const __half2 h0 = __floats2half2_rn(a0, a1);
    const __half2 h1 = __floats2half2_rn(a2, a3);
    float2 pk;
    pk.x = __uint_as_float(*reinterpret_cast<const unsigned int*>(&h0));
    pk.y = __uint_as_float(*reinterpret_cast<const unsigned int*>(&h1));
    *reinterpret_cast<float2*>(dst) = pk;
}

__device__ __forceinline__ void load4h(const __half2* src, float& x0, float& x1,
                                       float& x2, float& x3) {
    const float2 raw = *reinterpret_cast<const float2*>(src);
    const __half2 ha = *reinterpret_cast<const __half2*>(&raw.x);
    const __half2 hb = *reinterpret_cast<const __half2*>(&raw.y);
    const float2 fa = __half22float2(ha);
    const float2 fb = __half22float2(hb);
    x0 = fa.x; x1 = fa.y; x2 = fb.x; x3 = fb.y;
}

// m16n8k16 row.col f16xf16 -> f32 accumulate
__device__ __forceinline__ void mma16816(float* c, unsigned a0, unsigned a1,
                                         unsigned a2, unsigned a3,
                                         unsigned b0, unsigned b1) {
    asm volatile(
        "mma.sync.aligned.m16n8k16.row.col.f32.f16.f16.f32 "
        "{%0,%1,%2,%3}, {%4,%5,%6,%7}, {%8,%9}, {%0,%1,%2,%3};\n"
        : "+f"(c[0]), "+f"(c[1]), "+f"(c[2]), "+f"(c[3])
        : "r"(a0), "r"(a1), "r"(a2), "r"(a3), "r"(b0), "r"(b1));
}

__global__ void conv_w3l_kernel(const float* __restrict__ W3l) {
    const int i = blockIdx.x * blockDim.x + threadIdx.x;   // 0..16383
    const int n = i >> 7, k = i & 127;
    g_W3lT[n * 128 + k] = __float2half(W3l[k * 128 + n]);
}

__global__ void __launch_bounds__(256, 3)
vae_fused_kernel(const float* __restrict__ rgb,  const float* __restrict__ pos,
                 const float* __restrict__ pos1, const float* __restrict__ pos2,
                 const int*   __restrict__ oi0,  const int* __restrict__ oi1,
                 const float* __restrict__ eps,
                 const float* __restrict__ W1l, const float* __restrict__ b1l,
                 const float* __restrict__ W1g, const float* __restrict__ b1g,
                 const float* __restrict__ W2l, const float* __restrict__ b2l,
                 const float* __restrict__ W2g, const float* __restrict__ b2g,
                 const float* __restrict__ W3l, const float* __restrict__ b3l,
                 const float* __restrict__ W3g, const float* __restrict__ b3g,
                 const float* __restrict__ Wlin, const float* __restrict__ blin,
                 float* __restrict__ out)
{
    extern __shared__ unsigned char smem_raw[];
    Smem& s = *reinterpret_cast<Smem*>(smem_raw);
    const int tid  = threadIdx.x;
    const int lane = tid & 31;
    const int g0   = blockIdx.x * 2;

    // ---------------- preamble ----------------------------------------------
    for (int i = tid; i < 64;  i += 256) s.w1l[i] = W1l[i];
    if (tid < 16) s.b1l[tid] = b1l[tid];
    if (tid < 32) s.b1g[tid] = b1g[tid];
    if (tid < 64) s.b2l[tid] = b2l[tid];
    for (int i = tid; i < 512; i += 256) s.w1g[i] = W1g[i];
    if (tid < 192) s.pos2l2[tid] = pos2[(size_t)g0 * 96 + tid];

    // ============ per-glimpse stages 1-3 ====================================
    for (int gi = 0; gi < 2; gi++) {
        const int g = g0 + gi;
        __syncthreads();
        if (tid < 128) s.cur[tid] = 0;
        if (tid < 32)  s.cur2[tid] = 0;
        for (int i = tid; i < 384; i += 256) s.pos1l[i] = pos1[(size_t)g * 384 + i];
        __syncthreads();

        // count phase
        if (tid < 128) {
            const int c2 = (int)(oi1[(size_t)g * 128 + tid] - g * CPG2);
            s.idx1[tid] = c2;
            atomicAdd(&s.cur2[c2], 1);
        }
        for (int p = tid; p < NPG; p += 256) {
            const size_t e = (size_t)g * NPG + p;
            float4 pt;
            pt.x = rgb[e];
            pt.y = pos[e * 3 + 0];
            pt.z = pos[e * 3 + 1];
            pt.w = pos[e * 3 + 2];
            s.B.pts[p] = pt;
            atomicAdd(&s.cur[oi0[e] - g * CPG], 1);
        }
        __syncthreads();

        // prefix sums; cur becomes alloc cursor
        if (tid < 32) {
            int v0 = s.cur[lane * 4 + 0], v1 = s.cur[lane * 4 + 1];
            int v2 = s.cur[lane * 4 + 2], v3 = s.cur[lane * 4 + 3];
            int lsum = v0 + v1 + v2 + v3;
            int sc = lsum;
            #pragma unroll
            for (int off = 1; off < 32; off <<= 1) {
                int n = __shfl_up_sync(0xffffffffu, sc, off);
                if (lane >= off) sc += n;
            }
            int e0 = sc - lsum;
            int e1 = e0 + v0, e2 = e1 + v1, e3 = e2 + v2;
            s.ofs[lane * 4 + 0] = (unsigned short)e0; s.cur[lane * 4 + 0] = e0;
            s.ofs[lane * 4 + 1] = (unsigned short)e1; s.cur[lane * 4 + 1] = e1;
            s.ofs[lane * 4 + 2] = (unsigned short)e2; s.cur[lane * 4 + 2] = e2;
            s.ofs[lane * 4 + 3] = (unsigned short)e3; s.cur[lane * 4 + 3] = e3;
        } else if (tid < 64) {
            int v = s.cur2[lane];
            int sc = v;
            #pragma unroll
            for (int off = 1; off < 32; off <<= 1) {
                int n = __shfl_up_sync(0xffffffffu, sc, off);
                if (lane >= off) sc += n;
            }
            s.ofs2[lane] = (unsigned short)(sc - v);
            s.cur2[lane] = sc - v;
        }
        __syncthreads();

        // scatter passes
        for (int p = tid; p < NPG; p += 256) {
            const int c = oi0[(size_t)g * NPG + p] - g * CPG;
            const int slot = atomicAdd(&s.cur[c], 1);
            s.order[slot] = (unsigned short)p;
        }
        if (tid < 128) {
            const int slot = atomicAdd(&s.cur2[s.idx1[tid]], 1);
            s.order2[slot] = (unsigned short)tid;
        }
        __syncthreads();

        // stage 1: gather edge MLP (4 -> 16) + mean
        {
            const int c    = tid >> 1;
            const int half = tid & 1;
            const int beg = (int)s.ofs[c];
            const int n   = s.cur[c] - beg;
            const float cx = s.pos1l[c * 3 + 0];
            const float cy = s.pos1l[c * 3 + 1];
            const float cz = s.pos1l[c * 3 + 2];
            float wb[8], w0r[8], w1r[8], w2r[8], w3r[8];
            #pragma unroll
            for (int j8 = 0; j8 < 8; j8++) {
                const int j = half * 8 + j8;
                wb[j8]  = s.b1l[j];
                w0r[j8] = s.w1l[j];
                w1r[j8] = s.w1l[16 + j];
                w2r[j8] = s.w1l[32 + j];
                w3r[j8] = s.w1l[48 + j];
            }
            float acc[8];
            #pragma unroll
            for (int j8 = 0; j8 < 8; j8++) acc[j8] = 0.0f;
            for (int i = 0; i < n; i++) {
                const float4 pt = s.B.pts[(int)s.order[beg + i]];
                const float rx = pt.y - cx, ry = pt.z - cy, rz = pt.w - cz;
                #pragma unroll
                for (int j8 = 0; j8 < 8; j8++) {
                    float a = wb[j8];
                    a = fmaf(pt.x, w0r[j8], a);
                    a = fmaf(rx,   w1r[j8], a);
                    a = fmaf(ry,   w2r[j8], a);
                    a = fmaf(rz,   w3r[j8], a);
                    acc[j8] += celu1(a);
                }
            }
            const float inv = 1.0f / fmaxf((float)n, 1.0f);
            #pragma unroll
            for (int j8 = 0; j8 < 8; j8++)
                s.agg[c * 16 + half * 8 + j8] = acc[j8] * inv;
        }
        __syncthreads();

        // stage 2: f1 = celu(mean1 @ W1g + b1g)  [128][32] -> fp16
        {
            const int jq = tid & 7;
            const int cg = tid >> 3;
            const float4* Wq = reinterpret_cast<const float4*>(s.w1g); // [16][8]
            float acc[4][4];
            #pragma unroll
            for (int c4 = 0; c4 < 4; c4++)
                #pragma unroll
                for (int u = 0; u < 4; u++) acc[c4][u] = s.b1g[jq * 4 + u];
            #pragma unroll
            for (int k = 0; k < 16; k++) {
                const float4 wv = Wq[k * 8 + jq];
                #pragma unroll
                for (int c4 = 0; c4 < 4; c4++) {
                    const float x = s.agg[(cg * 4 + c4) * 16 + k];
                    FMA4(acc[c4], x, wv);
                }
            }
            #pragma unroll
            for (int c4 = 0; c4 < 4; c4++) {
                const int c = cg * 4 + c4;
                pack2h2(celu1(acc[c4][0]), celu1(acc[c4][1]),
                        celu1(acc[c4][2]), celu1(acc[c4][3]),
                        &s.A.f1h[c * 16 + jq * 2]);
            }
        }
        __syncthreads();

        // stage 3a: edge MLP (35 -> 64) into h2 (fp16) — FFMA2
        {
            const int jq = tid & 15;
            const int eg = tid >> 4;
            const ulonglong2* Wq = reinterpret_cast<const ulonglong2*>(W2l); // [35][16]q
            const float4 bb = reinterpret_cast<const float4*>(s.b2l)[jq];
            const u64t b01 = pack2(bb.x, bb.y), b23 = pack2(bb.z, bb.w);
            u64t acc[8][2];
            #pragma unroll
            for (int e = 0; e < 8; e++) { acc[e][0] = b01; acc[e][1] = b23; }
            #pragma unroll
            for (int kq = 0; kq < 8; kq++) {
                const ulonglong2 wa = Wq[(kq * 4 + 0) * 16 + jq];
                const ulonglong2 wb = Wq[(kq * 4 + 1) * 16 + jq];
                const ulonglong2 wc = Wq[(kq * 4 + 2) * 16 + jq];
                const ulonglong2 wd = Wq[(kq * 4 + 3) * 16 + jq];
                #pragma unroll
                for (int e = 0; e < 8; e++) {
                    float x0, x1, x2, x3;
                    load4h(&s.A.f1h[(eg * 8 + e) * 16 + kq * 2], x0, x1, x2, x3);
                    const u64t s0 = splat2(x0), s1 = splat2(x1);
                    const u64t s2 = splat2(x2), s3 = splat2(x3);
                    FMA2P(acc[e], s0, wa);
                    FMA2P(acc[e], s1, wb);
                    FMA2P(acc[e], s2, wc);
                    FMA2P(acc[e], s3, wd);
                }
            }
            #pragma unroll
            for (int k2 = 0; k2 < 3; k2++) {
                const ulonglong2 wv = Wq[(32 + k2) * 16 + jq];
                #pragma unroll
                for (int e = 0; e < 8; e++) {
                    const int ee = eg * 8 + e;
                    const float r = s.pos1l[ee * 3 + k2]
                                  - s.pos2l2[gi * 96 + s.idx1[ee] * 3 + k2];
                    const u64t r2 = splat2(r);
                    FMA2P(acc[e], r2, wv);
                }
            }
            #pragma unroll
            for (int e = 0; e < 8; e++) {
                const int ee = eg * 8 + e;
                float a0, a1, a2, a3;
                unpack2(acc[e][0], a0, a1);
                unpack2(acc[e][1], a2, a3);
                pack2h2(celu1(a0), celu1(a1), celu1(a2), celu1(a3),
                        &s.B.h2[ee * 32 + jq * 2]);
            }
        }
        __syncthreads();

        // stage 3b: gather-reduce h2 -> mean2h[gi] [32][64] fp16
        {
            const int c2 = tid >> 3;
            const int f8 = tid & 7;
            const int beg = (int)s.ofs2[c2];
            const int n   = s.cur2[c2] - beg;
            float acc[8];
            #pragma unroll
            for (int k = 0; k < 8; k++) acc[k] = 0.0f;
            for (int i = 0; i < n; i++) {
                const int e = (int)s.order2[beg + i];
                float x0, x1, x2, x3, x4, x5, x6, x7;
                load4h(&s.B.h2[e * 32 + f8 * 4],     x0, x1, x2, x3);
                load4h(&s.B.h2[e * 32 + f8 * 4 + 2], x4, x5, x6, x7);
                acc[0] += x0; acc[1] += x1; acc[2] += x2; acc[3] += x3;
                acc[4] += x4; acc[5] += x5; acc[6] += x6; acc[7] += x7;
            }
            const float inv = 1.0f / fmaxf((float)n, 1.0f);
            pack2h2(acc[0] * inv, acc[1] * inv, acc[2] * inv, acc[3] * inv,
                    &s.mean2h[gi * 1024 + c2 * 32 + f8 * 4]);
            pack2h2(acc[4] * inv, acc[5] * inv, acc[6] * inv, acc[7] * inv,
                    &s.mean2h[gi * 1024 + c2 * 32 + f8 * 4 + 2]);
        }
    }
    __syncthreads();

    // ============ joint stages 4-7 ==========================================

    // stage 4: f2 = celu(mean2 @ W2g + b2g)  [2][32][128] -> fp16 — FFMA2
    {
        const int jq = tid & 31;
        const int cg = tid >> 5;
        const ulonglong2* Wq = reinterpret_cast<const ulonglong2*>(W2g); // [64][32]q
        const float4 bb = reinterpret_cast<const float4*>(b2g)[jq];
        const u64t b01 = pack2(bb.x, bb.y), b23 = pack2(bb.z, bb.w);
        u64t acc[2][4][2];
        #pragma unroll
        for (int gi = 0; gi < 2; gi++)
            #pragma unroll
            for (int c4 = 0; c4 < 4; c4++) { acc[gi][c4][0] = b01; acc[gi][c4][1] = b23; }
        #pragma unroll 2
        for (int kq = 0; kq < 16; kq++) {
            const ulonglong2 wa = Wq[(kq * 4 + 0) * 32 + jq];
            const ulonglong2 wb = Wq[(kq * 4 + 1) * 32 + jq];
            const ulonglong2 wc = Wq[(kq * 4 + 2) * 32 + jq];
            const ulonglong2 wd = Wq[(kq * 4 + 3) * 32 + jq];
            #pragma unroll
            for (int gi = 0; gi < 2; gi++)
                #pragma unroll
                for (int c4 = 0; c4 < 4; c4++) {
                    float x0, x1, x2, x3;
                    load4h(&s.mean2h[gi * 1024 + (cg * 4 + c4) * 32 + kq * 2],
                           x0, x1, x2, x3);
                    const u64t s0 = splat2(x0), s1 = splat2(x1);
                    const u64t s2 = splat2(x2), s3 = splat2(x3);
                    FMA2P(acc[gi][c4], s0, wa);
                    FMA2P(acc[gi][c4], s1, wb);
                    FMA2P(acc[gi][c4], s2, wc);
                    FMA2P(acc[gi][c4], s3, wd);
                }
        }
        #pragma unroll
        for (int gi = 0; gi < 2; gi++)
            #pragma unroll
            for (int c4 = 0; c4 < 4; c4++) {
                float a0, a1, a2, a3;
                unpack2(acc[gi][c4][0], a0, a1);
                unpack2(acc[gi][c4][1], a2, a3);
                pack2h2(celu1(a0), celu1(a1), celu1(a2), celu1(a3),
                        &s.B.f2h[(gi * 32 + cg * 4 + c4) * 64 + jq * 2]);
            }
    }
    __syncthreads();

    // stage 5: level-3 edge MLP (131 -> 128) via tensor-core mma -------------
    // D[64, 128] = f2h[64, 128] @ W3lT_h^T, fp32 accum; bias/relpos/celu epilogue
    {
        const int w  = tid >> 5;
        const int m  = w & 3;          // mtile: rows m*16 .. m*16+15
        const int nh = w >> 2;         // n half: 0 or 1 (64 cols)
        const int r  = lane >> 2;      // 0..7
        const int tq = lane & 3;       // 0..3
        const int rowA0 = m * 16 + r;
        const int rowA1 = rowA0 + 8;
        float c[8][4];
        #pragma unroll
        for (int nt = 0; nt < 8; nt++) {
            c[nt][0] = 0.f; c[nt][1] = 0.f; c[nt][2] = 0.f; c[nt][3] = 0.f;
        }
        #pragma unroll
        for (int ks = 0; ks < 8; ks++) {
            const unsigned a0 = *reinterpret_cast<const unsigned*>(&s.B.f2h[rowA0 * 64 + ks * 8 + tq]);
            const unsigned a1 = *reinterpret_cast<const unsigned*>(&s.B.f2h[rowA1 * 64 + ks * 8 + tq]);
            const unsigned a2 = *reinterpret_cast<const unsigned*>(&s.B.f2h[rowA0 * 64 + ks * 8 + tq + 4]);
            const unsigned a3 = *reinterpret_cast<const unsigned*>(&s.B.f2h[rowA1 * 64 + ks * 8 + tq + 4]);
            #pragma unroll
            for (int nt = 0; nt < 8; nt++) {
                const int nb = nh * 64 + nt * 8 + r;   // B fragment column
                const unsigned b0 = *reinterpret_cast<const unsigned*>(&g_W3lT[nb * 128 + ks * 16 + tq * 2]);
                const unsigned b1 = *reinterpret_cast<const unsigned*>(&g_W3lT[nb * 128 + ks * 16 + tq * 2 + 8]);
                mma16816(c[nt], a0, a1, a2, a3, b0, b1);
            }
        }
        __syncthreads();   // all f2h reads done; B union becomes psum2
        const int gi = m >> 1;
        const int e0 = rowA0 & 31;
        const int e1 = rowA1 & 31;
        const float r00 = s.pos2l2[gi * 96 + e0 * 3 + 0];
        const float r01 = s.pos2l2[gi * 96 + e0 * 3 + 1];
        const float r02 = s.pos2l2[gi * 96 + e0 * 3 + 2];
        const float r10 = s.pos2l2[gi * 96 + e1 * 3 + 0];
        const float r11 = s.pos2l2[gi * 96 + e1 * 3 + 1];
        const float r12 = s.pos2l2[gi * 96 + e1 * 3 + 2];
        const int slot = (m & 1) * 8 + r;
        #pragma unroll
        for (int nt = 0; nt < 8; nt++) {
            const int nbase = nh * 64 + nt * 8 + tq * 2;   // C fragment columns
            #pragma unroll
            for (int u = 0; u < 2; u++) {
                const int n = nbase + u;
                const float bias = b3l[n];
                const float w0 = W3l[128 * 128 + n];
                const float w1 = W3l[129 * 128 + n];
                const float w2 = W3l[130 * 128 + n];
                const float v0 = c[nt][u]     + bias + r00 * w0 + r01 * w1 + r02 * w2;
                const float v1 = c[nt][2 + u] + bias + r10 * w0 + r11 * w1 + r12 * w2;
                s.B.psum2[slot * 256 + gi * 128 + n] = celu1(v0) + celu1(v1);
            }
        }
    }
    __syncthreads();
    {
        const int gi = tid >> 7;
        const int j  = tid & 127;
        float sum = 0.0f;
        #pragma unroll
        for (int sl = 0; sl < 16; sl++) sum += s.B.psum2[sl * 256 + gi * 128 + j];
        s.gsum[gi * 128 + j] = sum;
    }
    __syncthreads();

    // stage 6: f = celu((gsum/32) @ W3g + b3g), both glimpses
    {
        const int j = tid;
        float s0 = 0.0f, s1 = 0.0f;
        #pragma unroll 8
        for (int k = 0; k < 128; k++) {
            const float w = W3g[k * 256 + j];
            s0 = fmaf(s.gsum[k],       w, s0);
            s1 = fmaf(s.gsum[128 + k], w, s1);
        }
        const float bj = b3g[j];
        const float f0 = celu1(fmaf(s0, 0.03125f, bj));
        const float f1 = celu1(fmaf(s1, 0.03125f, bj));
        s.fvec[j] = f0;
        s.fvec[256 + j] = f1;
        out[OFF_F + (size_t)g0 * 256 + j] = f0;
        out[OFF_F + (size_t)(g0 + 1) * 256 + j] = f1;
    }
    __syncthreads();

    // stage 7: out = f @ Wlin + blin, both glimpses
    {
        const int j = tid;
        const float bj = blin[j];
        float a0 = bj, a1 = bj;
        #pragma unroll 8
        for (int k = 0; k < 256; k++) {
            const float w = Wlin[k * 256 + j];
            a0 = fmaf(s.fvec[k],       w, a0);
            a1 = fmaf(s.fvec[256 + k], w, a1);
        }
        s.outv[j] = a0;
        s.outv[256 + j] = a1;
    }
    __syncthreads();

    if (tid < 128) {
        #pragma unroll
        for (int gi = 0; gi < 2; gi++) {
            const size_t g = g0 + gi;
            const float mu = s.outv[gi * 256 + tid];
            const float sg = s.outv[gi * 256 + 128 + tid];
            const float sigma = fmaxf(sg, 0.0f) + log1pf(__expf(-fabsf(sg)));
            const float z = fmaf(sigma, eps[g * 128 + tid], mu);
            out[OFF_MU    + g * 128 + tid] = mu;
            out[OFF_SIGMA + g * 128 + tid] = sigma;
            if (tid < 64) out[OFF_ZWHAT + g * 64 + tid] = z;
            else          out[OFF_ZMASK + g * 64 + (tid - 64)] = z;
        }
    }
}

extern "C" void kernel_launch(void* const* d_in, const int* in_sizes, int n_in,
                              void* d_out, int out_size)
{
    const float* rgb  = (const float*)d_in[0];
    const float* pos  = (const float*)d_in[1];
    const float* pos1 = (const float*)d_in[2];
    const float* pos2 = (const float*)d_in[3];
    const int*   oi0  = (const int*)  d_in[4];
    const int*   oi1  = (const int*)  d_in[5];
    const float* eps  = (const float*)d_in[7];
    const float* W1l  = (const float*)d_in[8];
    const float* b1l  = (const float*)d_in[9];
    const float* W1g  = (const float*)d_in[10];
    const float* b1g  = (const float*)d_in[11];
    const float* W2l  = (const float*)d_in[12];
    const float* b2l  = (const float*)d_in[13];
    const float* W2g  = (const float*)d_in[14];
    const float* b2g  = (const float*)d_in[15];
    const float* W3l  = (const float*)d_in[16];
    const float* b3l  = (const float*)d_in[17];
    const float* W3g  = (const float*)d_in[18];
    const float* b3g  = (const float*)d_in[19];
    const float* Wlin = (const float*)d_in[20];
    const float* blin = (const float*)d_in[21];
    float* out = (float*)d_out;

    conv_w3l_kernel<<<64, 256>>>(W3l);

    cudaFuncSetAttribute(vae_fused_kernel,
                         cudaFuncAttributeMaxDynamicSharedMemorySize,
                         (int)sizeof(Smem));
    vae_fused_kernel<<<NG / 2, 256, sizeof(Smem)>>>(
        rgb, pos, pos1, pos2, oi0, oi1, eps,
        W1l, b1l, W1g, b1g, W2l, b2l, W2g, b2g,
        W3l, b3l, W3g, b3g, Wlin, blin, out);
}

// round 15
// speedup vs baseline: 2.2273x; 1.0564x over previous
#include <cuda_runtime.h>
#include <cuda_fp16.h>
#include <math.h>

// Problem constants
#define NG    2048
#define NPG   512
#define CPG   128
#define CPG2  32

// Output layout (float32)
#define OFF_ZWHAT 0
#define OFF_ZMASK 131072
#define OFF_MU    262144
#define OFF_SIGMA 524288
#define OFF_F     786432

// fp16 transposed weight copies: T[n][k]
__device__ __half g_W3lT[128 * 128];
__device__ __half g_W2gT[128 * 64];
__device__ __half g_W2lT[64 * 32];

struct __align__(16) Smem {
    float w1l[64];      // [4][16]
    float b1l[16];
    float b1g[32];
    float b2l[64];
    float w1g[512];     // [16][32]
    float pos1l[384];   // [128][3]      (per-glimpse, reloaded)
    float pos2l2[192];  // [2][32][3]    (both glimpses)
    int   idx1[128];
    int   cur[128];
    int   cur2[32];
    unsigned short ofs[128];
    unsigned short ofs2[32];
    unsigned short order[512];
    unsigned short order2[128];
    float agg[2048];        // stage1 mean [128][16] (per-glimpse reuse)
    __half2 mean2h[2048];   // [2][32][32h2]
    float gsum[256];
    float fvec[512];
    float outv[512];
    union {                 // 8 KB (single-instance, per-glimpse reuse)
        __half2 f1h[2048];  // [128][16h2]
    } A;
    union {                 // 16 KB (single-instance, per-glimpse reuse)
        float4  pts[512];
        __half2 h2[4096];   // [128][32h2]
        __half2 f2h[4096];  // [2][32][64h2] joint stage4->5 (A operand for mma)
        float   psum2[4096];// [16 slots][256] stage-5 partial sums
    } B;
};

typedef unsigned long long u64t;

__device__ __forceinline__ float celu1(float x) {
    return fmaxf(x, 0.0f) + (__expf(fminf(x, 0.0f)) - 1.0f);
}

// ---- packed fp32x2 helpers (Blackwell FFMA2) ----
__device__ __forceinline__ u64t splat2(float x) {
    u64t r; asm("mov.b64 %0, {%1, %1};" : "=l"(r) : "f"(x)); return r;
}
__device__ __forceinline__ u64t pack2(float lo, float hi) {
    u64t r; asm("mov.b64 %0, {%1, %2};" : "=l"(r) : "f"(lo), "f"(hi)); return r;
}
__device__ __forceinline__ void unpack2(u64t v, float& lo, float& hi) {
    asm("mov.b64 {%0, %1}, %2;" : "=f"(lo), "=f"(hi) : "l"(v));
}
__device__ __forceinline__ void ffma2(u64t& acc, u64t a, u64t b) {
    asm("fma.rn.f32x2 %0, %1, %2, %0;" : "+l"(acc) : "l"(a), "l"(b));
}
#define FMA2P(accp, xs2, wv2) \
    { ffma2((accp)[0], (xs2), (wv2).x); ffma2((accp)[1], (xs2), (wv2).y); }

#define FMA4(Aacc, xs, wv) \
    { Aacc[0] = fmaf((xs), (wv).x, Aacc[0]); Aacc[1] = fmaf((xs), (wv).y, Aacc[1]); \
      Aacc[2] = fmaf((xs), (wv).z, Aacc[2]); Aacc[3] = fmaf((xs), (wv).w, Aacc[3]); }

__device__ __forceinline__ void pack2h2(float a0, float a1, float a2, float a3,
                                        __half2* dst) {
    const __half2 h0 = __floats2half2_rn(a0, a1);
    const __half2 h1 = __floats2half2_rn(a2, a3);
    float2 pk;
    pk.x = __uint_as_float(*reinterpret_cast<const unsigned int*>(&h0));
    pk.y = __uint_as_float(*reinterpret_cast<const unsigned int*>(&h1));
    *reinterpret_cast<float2*>(dst) = pk;
}

__device__ __forceinline__ void load4h(const __half2* src, float& x0, float& x1,
                                       float& x2, float& x3) {
    const float2 raw = *reinterpret_cast<const float2*>(src);
    const __half2 ha = *reinterpret_cast<const __half2*>(&raw.x);
    const __half2 hb = *reinterpret_cast<const __half2*>(&raw.y);
    const float2 fa = __half22float2(ha);
    const float2 fb = __half22float2(hb);
    x0 = fa.x; x1 = fa.y; x2 = fb.x; x3 = fb.y;
}

// m16n8k16 row.col f16xf16 -> f32 accumulate
__device__ __forceinline__ void mma16816(float* c, unsigned a0, unsigned a1,
                                         unsigned a2, unsigned a3,
                                         unsigned b0, unsigned b1) {
    asm volatile(
        "mma.sync.aligned.m16n8k16.row.col.f32.f16.f16.f32 "
        "{%0,%1,%2,%3}, {%4,%5,%6,%7}, {%8,%9}, {%0,%1,%2,%3};\n"
        : "+f"(c[0]), "+f"(c[1]), "+f"(c[2]), "+f"(c[3])
        : "r"(a0), "r"(a1), "r"(a2), "r"(a3), "r"(b0), "r"(b1));
}

__global__ void conv_weights_kernel(const float* __restrict__ W3l,
                                    const float* __restrict__ W2g,
                                    const float* __restrict__ W2l) {
    const int i = blockIdx.x * blockDim.x + threadIdx.x;
    if (i < 16384) {
        const int n = i >> 7, k = i & 127;
        g_W3lT[n * 128 + k] = __float2half(W3l[k * 128 + n]);
    } else if (i < 16384 + 8192) {
        const int j = i - 16384;
        const int n = j >> 6, k = j & 63;
        g_W2gT[n * 64 + k] = __float2half(W2g[k * 128 + n]);
    } else if (i < 16384 + 8192 + 2048) {
        const int j = i - 24576;
        const int n = j >> 5, k = j & 31;
        g_W2lT[n * 32 + k] = __float2half(W2l[k * 64 + n]);
    }
}

__global__ void __launch_bounds__(256, 3)
vae_fused_kernel(const float* __restrict__ rgb,  const float* __restrict__ pos,
                 const float* __restrict__ pos1, const float* __restrict__ pos2,
                 const int*   __restrict__ oi0,  const int* __restrict__ oi1,
                 const float* __restrict__ eps,
                 const float* __restrict__ W1l, const float* __restrict__ b1l,
                 const float* __restrict__ W1g, const float* __restrict__ b1g,
                 const float* __restrict__ W2l, const float* __restrict__ b2l,
                 const float* __restrict__ W2g, const float* __restrict__ b2g,
                 const float* __restrict__ W3l, const float* __restrict__ b3l,
                 const float* __restrict__ W3g, const float* __restrict__ b3g,
                 const float* __restrict__ Wlin, const float* __restrict__ blin,
                 float* __restrict__ out)
{
    extern __shared__ unsigned char smem_raw[];
    Smem& s = *reinterpret_cast<Smem*>(smem_raw);
    const int tid  = threadIdx.x;
    const int lane = tid & 31;
    const int g0   = blockIdx.x * 2;

    // ---------------- preamble ----------------------------------------------
    for (int i = tid; i < 64;  i += 256) s.w1l[i] = W1l[i];
    if (tid < 16) s.b1l[tid] = b1l[tid];
    if (tid < 32) s.b1g[tid] = b1g[tid];
    if (tid < 64) s.b2l[tid] = b2l[tid];
    for (int i = tid; i < 512; i += 256) s.w1g[i] = W1g[i];
    if (tid < 192) s.pos2l2[tid] = pos2[(size_t)g0 * 96 + tid];

    // ============ per-glimpse stages 1-3 ====================================
    for (int gi = 0; gi < 2; gi++) {
        const int g = g0 + gi;
        __syncthreads();
        if (tid < 128) s.cur[tid] = 0;
        if (tid < 32)  s.cur2[tid] = 0;
        for (int i = tid; i < 384; i += 256) s.pos1l[i] = pos1[(size_t)g * 384 + i];
        __syncthreads();

        // count phase
        if (tid < 128) {
            const int c2 = (int)(oi1[(size_t)g * 128 + tid] - g * CPG2);
            s.idx1[tid] = c2;
            atomicAdd(&s.cur2[c2], 1);
        }
        for (int p = tid; p < NPG; p += 256) {
            const size_t e = (size_t)g * NPG + p;
            float4 pt;
            pt.x = rgb[e];
            pt.y = pos[e * 3 + 0];
            pt.z = pos[e * 3 + 1];
            pt.w = pos[e * 3 + 2];
            s.B.pts[p] = pt;
            atomicAdd(&s.cur[oi0[e] - g * CPG], 1);
        }
        __syncthreads();

        // prefix sums; cur becomes alloc cursor
        if (tid < 32) {
            int v0 = s.cur[lane * 4 + 0], v1 = s.cur[lane * 4 + 1];
            int v2 = s.cur[lane * 4 + 2], v3 = s.cur[lane * 4 + 3];
            int lsum = v0 + v1 + v2 + v3;
            int sc = lsum;
            #pragma unroll
            for (int off = 1; off < 32; off <<= 1) {
                int n = __shfl_up_sync(0xffffffffu, sc, off);
                if (lane >= off) sc += n;
            }
            int e0 = sc - lsum;
            int e1 = e0 + v0, e2 = e1 + v1, e3 = e2 + v2;
            s.ofs[lane * 4 + 0] = (unsigned short)e0; s.cur[lane * 4 + 0] = e0;
            s.ofs[lane * 4 + 1] = (unsigned short)e1; s.cur[lane * 4 + 1] = e1;
            s.ofs[lane * 4 + 2] = (unsigned short)e2; s.cur[lane * 4 + 2] = e2;
            s.ofs[lane * 4 + 3] = (unsigned short)e3; s.cur[lane * 4 + 3] = e3;
        } else if (tid < 64) {
            int v = s.cur2[lane];
            int sc = v;
            #pragma unroll
            for (int off = 1; off < 32; off <<= 1) {
                int n = __shfl_up_sync(0xffffffffu, sc, off);
                if (lane >= off) sc += n;
            }
            s.ofs2[lane] = (unsigned short)(sc - v);
            s.cur2[lane] = sc - v;
        }
        __syncthreads();

        // scatter passes
        for (int p = tid; p < NPG; p += 256) {
            const int c = oi0[(size_t)g * NPG + p] - g * CPG;
            const int slot = atomicAdd(&s.cur[c], 1);
            s.order[slot] = (unsigned short)p;
        }
        if (tid < 128) {
            const int slot = atomicAdd(&s.cur2[s.idx1[tid]], 1);
            s.order2[slot] = (unsigned short)tid;
        }
        __syncthreads();

        // stage 1: gather edge MLP (4 -> 16) + mean
        {
            const int c    = tid >> 1;
            const int half = tid & 1;
            const int beg = (int)s.ofs[c];
            const int n   = s.cur[c] - beg;
            const float cx = s.pos1l[c * 3 + 0];
            const float cy = s.pos1l[c * 3 + 1];
            const float cz = s.pos1l[c * 3 + 2];
            float wb[8], w0r[8], w1r[8], w2r[8], w3r[8];
            #pragma unroll
            for (int j8 = 0; j8 < 8; j8++) {
                const int j = half * 8 + j8;
                wb[j8]  = s.b1l[j];
                w0r[j8] = s.w1l[j];
                w1r[j8] = s.w1l[16 + j];
                w2r[j8] = s.w1l[32 + j];
                w3r[j8] = s.w1l[48 + j];
            }
            float acc[8];
            #pragma unroll
            for (int j8 = 0; j8 < 8; j8++) acc[j8] = 0.0f;
            for (int i = 0; i < n; i++) {
                const float4 pt = s.B.pts[(int)s.order[beg + i]];
                const float rx = pt.y - cx, ry = pt.z - cy, rz = pt.w - cz;
                #pragma unroll
                for (int j8 = 0; j8 < 8; j8++) {
                    float a = wb[j8];
                    a = fmaf(pt.x, w0r[j8], a);
                    a = fmaf(rx,   w1r[j8], a);
                    a = fmaf(ry,   w2r[j8], a);
                    a = fmaf(rz,   w3r[j8], a);
                    acc[j8] += celu1(a);
                }
            }
            const float inv = 1.0f / fmaxf((float)n, 1.0f);
            #pragma unroll
            for (int j8 = 0; j8 < 8; j8++)
                s.agg[c * 16 + half * 8 + j8] = acc[j8] * inv;
        }
        __syncthreads();

        // stage 2: f1 = celu(mean1 @ W1g + b1g)  [128][32] -> fp16
        {
            const int jq = tid & 7;
            const int cg = tid >> 3;
            const float4* Wq = reinterpret_cast<const float4*>(s.w1g); // [16][8]
            float acc[4][4];
            #pragma unroll
            for (int c4 = 0; c4 < 4; c4++)
                #pragma unroll
                for (int u = 0; u < 4; u++) acc[c4][u] = s.b1g[jq * 4 + u];
            #pragma unroll
            for (int k = 0; k < 16; k++) {
                const float4 wv = Wq[k * 8 + jq];
                #pragma unroll
                for (int c4 = 0; c4 < 4; c4++) {
                    const float x = s.agg[(cg * 4 + c4) * 16 + k];
                    FMA4(acc[c4], x, wv);
                }
            }
            #pragma unroll
            for (int c4 = 0; c4 < 4; c4++) {
                const int c = cg * 4 + c4;
                pack2h2(celu1(acc[c4][0]), celu1(acc[c4][1]),
                        celu1(acc[c4][2]), celu1(acc[c4][3]),
                        &s.A.f1h[c * 16 + jq * 2]);
            }
        }
        __syncthreads();

        // stage 3a: edge MLP (35 -> 64) via tensor-core mma -------------------
        // D[128,64] = f1h[128,32] @ W2lT^T; bias + relpos + celu -> h2 (fp16)
        {
            const int w  = tid >> 5;      // mtile 0..7: rows w*16 .. w*16+15
            const int r  = lane >> 2;     // 0..7
            const int tq = lane & 3;      // 0..3
            const int row0 = w * 16 + r;
            const int row1 = row0 + 8;
            float c[8][4];
            #pragma unroll
            for (int nt = 0; nt < 8; nt++) {
                c[nt][0] = 0.f; c[nt][1] = 0.f; c[nt][2] = 0.f; c[nt][3] = 0.f;
            }
            #pragma unroll
            for (int ks = 0; ks < 2; ks++) {
                const unsigned a0 = *reinterpret_cast<const unsigned*>(&s.A.f1h[row0 * 16 + ks * 8 + tq]);
                const unsigned a1 = *reinterpret_cast<const unsigned*>(&s.A.f1h[row1 * 16 + ks * 8 + tq]);
                const unsigned a2 = *reinterpret_cast<const unsigned*>(&s.A.f1h[row0 * 16 + ks * 8 + tq + 4]);
                const unsigned a3 = *reinterpret_cast<const unsigned*>(&s.A.f1h[row1 * 16 + ks * 8 + tq + 4]);
                #pragma unroll
                for (int nt = 0; nt < 8; nt++) {
                    const int nb = nt * 8 + r;
                    const unsigned b0 = *reinterpret_cast<const unsigned*>(&g_W2lT[nb * 32 + ks * 16 + tq * 2]);
                    const unsigned b1 = *reinterpret_cast<const unsigned*>(&g_W2lT[nb * 32 + ks * 16 + tq * 2 + 8]);
                    mma16816(c[nt], a0, a1, a2, a3, b0, b1);
                }
            }
            // epilogue: bias + relpos rows (32..34) + celu -> h2
            const int i0 = s.idx1[row0], i1 = s.idx1[row1];
            const float r00 = s.pos1l[row0 * 3 + 0] - s.pos2l2[gi * 96 + i0 * 3 + 0];
            const float r01 = s.pos1l[row0 * 3 + 1] - s.pos2l2[gi * 96 + i0 * 3 + 1];
            const float r02 = s.pos1l[row0 * 3 + 2] - s.pos2l2[gi * 96 + i0 * 3 + 2];
            const float r10 = s.pos1l[row1 * 3 + 0] - s.pos2l2[gi * 96 + i1 * 3 + 0];
            const float r11 = s.pos1l[row1 * 3 + 1] - s.pos2l2[gi * 96 + i1 * 3 + 1];
            const float r12 = s.pos1l[row1 * 3 + 2] - s.pos2l2[gi * 96 + i1 * 3 + 2];
            #pragma unroll
            for (int nt = 0; nt < 8; nt++) {
                const int nb0 = nt * 8 + tq * 2;
                const int nb1 = nb0 + 1;
                const float bi0 = s.b2l[nb0], bi1 = s.b2l[nb1];
                const float wa0 = W2l[32 * 64 + nb0], wa1 = W2l[32 * 64 + nb1];
                const float wb0 = W2l[33 * 64 + nb0], wb1 = W2l[33 * 64 + nb1];
                const float wc0 = W2l[34 * 64 + nb0], wc1 = W2l[34 * 64 + nb1];
                const float v00 = c[nt][0] + bi0 + r00 * wa0 + r01 * wb0 + r02 * wc0;
                const float v01 = c[nt][1] + bi1 + r00 * wa1 + r01 * wb1 + r02 * wc1;
                const float v10 = c[nt][2] + bi0 + r10 * wa0 + r11 * wb0 + r12 * wc0;
                const float v11 = c[nt][3] + bi1 + r10 * wa1 + r11 * wb1 + r12 * wc1;
                const int hcol = nt * 4 + tq;
                s.B.h2[row0 * 32 + hcol] = __floats2half2_rn(celu1(v00), celu1(v01));
                s.B.h2[row1 * 32 + hcol] = __floats2half2_rn(celu1(v10), celu1(v11));
            }
        }
        __syncthreads();

        // stage 3b: gather-reduce h2 -> mean2h[gi] [32][64] fp16
        {
            const int c2 = tid >> 3;
            const int f8 = tid & 7;
            const int beg = (int)s.ofs2[c2];
            const int n   = s.cur2[c2] - beg;
            float acc[8];
            #pragma unroll
            for (int k = 0; k < 8; k++) acc[k] = 0.0f;
            for (int i = 0; i < n; i++) {
                const int e = (int)s.order2[beg + i];
                float x0, x1, x2, x3, x4, x5, x6, x7;
                load4h(&s.B.h2[e * 32 + f8 * 4],     x0, x1, x2, x3);
                load4h(&s.B.h2[e * 32 + f8 * 4 + 2], x4, x5, x6, x7);
                acc[0] += x0; acc[1] += x1; acc[2] += x2; acc[3] += x3;
                acc[4] += x4; acc[5] += x5; acc[6] += x6; acc[7] += x7;
            }
            const float inv = 1.0f / fmaxf((float)n, 1.0f);
            pack2h2(acc[0] * inv, acc[1] * inv, acc[2] * inv, acc[3] * inv,
                    &s.mean2h[gi * 1024 + c2 * 32 + f8 * 4]);
            pack2h2(acc[4] * inv, acc[5] * inv, acc[6] * inv, acc[7] * inv,
                    &s.mean2h[gi * 1024 + c2 * 32 + f8 * 4 + 2]);
        }
    }
    __syncthreads();

    // ============ joint stages 4-7 ==========================================

    // stage 4: f2 = celu(mean2 @ W2g + b2g) via tensor-core mma ---------------
    // D[64,128] = mean2h[64,64] @ W2gT^T; +b2g, celu -> f2h (fp16)
    {
        const int w  = tid >> 5;
        const int m  = w & 3;          // mtile: rows m*16 .. m*16+15 (of 64)
        const int nh = w >> 2;         // n half: 0 or 1
        const int r  = lane >> 2;
        const int tq = lane & 3;
        const int row0 = m * 16 + r;
        const int row1 = row0 + 8;
        float c[8][4];
        #pragma unroll
        for (int nt = 0; nt < 8; nt++) {
            c[nt][0] = 0.f; c[nt][1] = 0.f; c[nt][2] = 0.f; c[nt][3] = 0.f;
        }
        #pragma unroll
        for (int ks = 0; ks < 4; ks++) {
            const unsigned a0 = *reinterpret_cast<const unsigned*>(&s.mean2h[row0 * 32 + ks * 8 + tq]);
            const unsigned a1 = *reinterpret_cast<const unsigned*>(&s.mean2h[row1 * 32 + ks * 8 + tq]);
            const unsigned a2 = *reinterpret_cast<const unsigned*>(&s.mean2h[row0 * 32 + ks * 8 + tq + 4]);
            const unsigned a3 = *reinterpret_cast<const unsigned*>(&s.mean2h[row1 * 32 + ks * 8 + tq + 4]);
            #pragma unroll
            for (int nt = 0; nt < 8; nt++) {
                const int nb = nh * 64 + nt * 8 + r;
                const unsigned b0 = *reinterpret_cast<const unsigned*>(&g_W2gT[nb * 64 + ks * 16 + tq * 2]);
                const unsigned b1 = *reinterpret_cast<const unsigned*>(&g_W2gT[nb * 64 + ks * 16 + tq * 2 + 8]);
                mma16816(c[nt], a0, a1, a2, a3, b0, b1);
            }
        }
        #pragma unroll
        for (int nt = 0; nt < 8; nt++) {
            const int nb0 = nh * 64 + nt * 8 + tq * 2;
            const float bi0 = b2g[nb0], bi1 = b2g[nb0 + 1];
            const int hcol = nh * 32 + nt * 4 + tq;
            s.B.f2h[row0 * 64 + hcol] =
                __floats2half2_rn(celu1(c[nt][0] + bi0), celu1(c[nt][1] + bi1));
            s.B.f2h[row1 * 64 + hcol] =
                __floats2half2_rn(celu1(c[nt][2] + bi0), celu1(c[nt][3] + bi1));
        }
    }
    __syncthreads();

    // stage 5: level-3 edge MLP (131 -> 128) via tensor-core mma -------------
    {
        const int w  = tid >> 5;
        const int m  = w & 3;
        const int nh = w >> 2;
        const int r  = lane >> 2;
        const int tq = lane & 3;
        const int rowA0 = m * 16 + r;
        const int rowA1 = rowA0 + 8;
        float c[8][4];
        #pragma unroll
        for (int nt = 0; nt < 8; nt++) {
            c[nt][0] = 0.f; c[nt][1] = 0.f; c[nt][2] = 0.f; c[nt][3] = 0.f;
        }
        #pragma unroll
        for (int ks = 0; ks < 8; ks++) {
            const unsigned a0 = *reinterpret_cast<const unsigned*>(&s.B.f2h[rowA0 * 64 + ks * 8 + tq]);
            const unsigned a1 = *reinterpret_cast<const unsigned*>(&s.B.f2h[rowA1 * 64 + ks * 8 + tq]);
            const unsigned a2 = *reinterpret_cast<const unsigned*>(&s.B.f2h[rowA0 * 64 + ks * 8 + tq + 4]);
            const unsigned a3 = *reinterpret_cast<const unsigned*>(&s.B.f2h[rowA1 * 64 + ks * 8 + tq + 4]);
            #pragma unroll
            for (int nt = 0; nt < 8; nt++) {
                const int nb = nh * 64 + nt * 8 + r;
                const unsigned b0 = *reinterpret_cast<const unsigned*>(&g_W3lT[nb * 128 + ks * 16 + tq * 2]);
                const unsigned b1 = *reinterpret_cast<const unsigned*>(&g_W3lT[nb * 128 + ks * 16 + tq * 2 + 8]);
                mma16816(c[nt], a0, a1, a2, a3, b0, b1);
            }
        }
        __syncthreads();   // all f2h reads done; B union becomes psum2
        const int gi = m >> 1;
        const int e0 = rowA0 & 31;
        const int e1 = rowA1 & 31;
        const float r00 = s.pos2l2[gi * 96 + e0 * 3 + 0];
        const float r01 = s.pos2l2[gi * 96 + e0 * 3 + 1];
        const float r02 = s.pos2l2[gi * 96 + e0 * 3 + 2];
        const float r10 = s.pos2l2[gi * 96 + e1 * 3 + 0];
        const float r11 = s.pos2l2[gi * 96 + e1 * 3 + 1];
        const float r12 = s.pos2l2[gi * 96 + e1 * 3 + 2];
        const int slot = (m & 1) * 8 + r;
        #pragma unroll
        for (int nt = 0; nt < 8; nt++) {
            const int nbase = nh * 64 + nt * 8 + tq * 2;
            #pragma unroll
            for (int u = 0; u < 2; u++) {
                const int n = nbase + u;
                const float bias = b3l[n];
                const float w0 = W3l[128 * 128 + n];
                const float w1 = W3l[129 * 128 + n];
                const float w2 = W3l[130 * 128 + n];
                const float v0 = c[nt][u]     + bias + r00 * w0 + r01 * w1 + r02 * w2;
                const float v1 = c[nt][2 + u] + bias + r10 * w0 + r11 * w1 + r12 * w2;
                s.B.psum2[slot * 256 + gi * 128 + n] = celu1(v0) + celu1(v1);
            }
        }
    }
    __syncthreads();
    {
        const int gi = tid >> 7;
        const int j  = tid & 127;
        float sum = 0.0f;
        #pragma unroll
        for (int sl = 0; sl < 16; sl++) sum += s.B.psum2[sl * 256 + gi * 128 + j];
        s.gsum[gi * 128 + j] = sum;
    }
    __syncthreads();

    // stage 6: f = celu((gsum/32) @ W3g + b3g), both glimpses
    {
        const int j = tid;
        float s0 = 0.0f, s1 = 0.0f;
        #pragma unroll 8
        for (int k = 0; k < 128; k++) {
            const float w = W3g[k * 256 + j];
            s0 = fmaf(s.gsum[k],       w, s0);
            s1 = fmaf(s.gsum[128 + k], w, s1);
        }
        const float bj = b3g[j];
        const float f0 = celu1(fmaf(s0, 0.03125f, bj));
        const float f1 = celu1(fmaf(s1, 0.03125f, bj));
        s.fvec[j] = f0;
        s.fvec[256 + j] = f1;
        out[OFF_F + (size_t)g0 * 256 + j] = f0;
        out[OFF_F + (size_t)(g0 + 1) * 256 + j] = f1;
    }
    __syncthreads();

    // stage 7: out = f @ Wlin + blin, both glimpses
    {
        const int j = tid;
        const float bj = blin[j];
        float a0 = bj, a1 = bj;
        #pragma unroll 8
        for (int k = 0; k < 256; k++) {
            const float w = Wlin[k * 256 + j];
            a0 = fmaf(s.fvec[k],       w, a0);
            a1 = fmaf(s.fvec[256 + k], w, a1);
        }
        s.outv[j] = a0;
        s.outv[256 + j] = a1;
    }
    __syncthreads();

    if (tid < 128) {
        #pragma unroll
        for (int gi = 0; gi < 2; gi++) {
            const size_t g = g0 + gi;
            const float mu = s.outv[gi * 256 + tid];
            const float sg = s.outv[gi * 256 + 128 + tid];
            const float sigma = fmaxf(sg, 0.0f) + log1pf(__expf(-fabsf(sg)));
            const float z = fmaf(sigma, eps[g * 128 + tid], mu);
            out[OFF_MU    + g * 128 + tid] = mu;
            out[OFF_SIGMA + g * 128 + tid] = sigma;
            if (tid < 64) out[OFF_ZWHAT + g * 64 + tid] = z;
            else          out[OFF_ZMASK + g * 64 + (tid - 64)] = z;
        }
    }
}

extern "C" void kernel_launch(void* const* d_in, const int* in_sizes, int n_in,
                              void* d_out, int out_size)
{
    const float* rgb  = (const float*)d_in[0];
    const float* pos  = (const float*)d_in[1];
    const float* pos1 = (const float*)d_in[2];
    const float* pos2 = (const float*)d_in[3];
    const int*   oi0  = (const int*)  d_in[4];
    const int*   oi1  = (const int*)  d_in[5];
    const float* eps  = (const float*)d_in[7];
    const float* W1l  = (const float*)d_in[8];
    const float* b1l  = (const float*)d_in[9];
    const float* W1g  = (const float*)d_in[10];
    const float* b1g  = (const float*)d_in[11];
    const float* W2l  = (const float*)d_in[12];
    const float* b2l  = (const float*)d_in[13];
    const float* W2g  = (const float*)d_in[14];
    const float* b2g  = (const float*)d_in[15];
    const float* W3l  = (const float*)d_in[16];
    const float* b3l  = (const float*)d_in[17];
    const float* W3g  = (const float*)d_in[18];
    const float* b3g  = (const float*)d_in[19];
    const float* Wlin = (const float*)d_in[20];
    const float* blin = (const float*)d_in[21];
    float* out = (float*)d_out;

    conv_weights_kernel<<<104, 256>>>(W3l, W2g, W2l);

    cudaFuncSetAttribute(vae_fused_kernel,
                         cudaFuncAttributeMaxDynamicSharedMemorySize,
                         (int)sizeof(Smem));
    vae_fused_kernel<<<NG / 2, 256, sizeof(Smem)>>>(
        rgb, pos, pos1, pos2, oi0, oi1, eps,
        W1l, b1l, W1g, b1g, W2l, b2l, W2g, b2g,
        W3l, b3l, W3g, b3g, Wlin, blin, out);
}

// round 16
// speedup vs baseline: 2.9712x; 1.3340x over previous
#include <cuda_runtime.h>
#include <cuda_fp16.h>
#include <math.h>

// Problem constants
#define NG    2048
#define NPG   512
#define CPG   128
#define CPG2  32

// Output layout (float32)
#define OFF_ZWHAT 0
#define OFF_ZMASK 131072
#define OFF_MU    262144
#define OFF_SIGMA 524288
#define OFF_F     786432

// fp16 weights pre-packed in mma B-fragment order:
// entry index (ntile*KS + ks)*32 + lane holds half2{b0}, half2{b1}
__device__ __half2 g_W3lP[16 * 8 * 32 * 2 / 2 * 2];  // 16 ntiles x 8 ks x 32 lanes x 2 half2
__device__ __half2 g_W2gP[16 * 4 * 32 * 2];
__device__ __half2 g_W2lP[8 * 2 * 32 * 2];

struct __align__(16) Smem {
    float w1l[64];      // [4][16]
    float b1l[16];
    float b1g[32];
    float b2l[64];
    float w1g[512];     // [16][32]
    float pos1l[384];   // [128][3]      (per-glimpse, reloaded)
    float pos2l2[192];  // [2][32][3]    (both glimpses)
    int   idx1[128];
    int   cur[128];
    int   cur2[32];
    unsigned short ofs[128];
    unsigned short ofs2[32];
    unsigned short order[512];
    unsigned short order2[128];
    float agg[2048];        // stage1 mean [128][16] (per-glimpse reuse)
    __half2 mean2h[2048];   // [2][32][32h2]
    float gsum[256];
    float fvec[512];
    float outv[512];
    union {                 // 8 KB (single-instance, per-glimpse reuse)
        __half2 f1h[2048];  // [128][16h2]
    } A;
    union {                 // 16 KB (single-instance, per-glimpse reuse)
        float4  pts[512];
        __half2 h2[4096];   // [128][32h2]
        __half2 f2h[4096];  // [2][32][64h2] joint stage4->5 (A operand for mma)
        float   psum2[4096];// [16 slots][256] stage-5 partial sums
    } B;
};

typedef unsigned long long u64t;

__device__ __forceinline__ float celu1(float x) {
    return fmaxf(x, 0.0f) + (__expf(fminf(x, 0.0f)) - 1.0f);
}

#define FMA4(Aacc, xs, wv) \
    { Aacc[0] = fmaf((xs), (wv).x, Aacc[0]); Aacc[1] = fmaf((xs), (wv).y, Aacc[1]); \
      Aacc[2] = fmaf((xs), (wv).z, Aacc[2]); Aacc[3] = fmaf((xs), (wv).w, Aacc[3]); }

__device__ __forceinline__ void pack2h2(float a0, float a1, float a2, float a3,
                                        __half2* dst) {
    const __half2 h0 = __floats2half2_rn(a0, a1);
    const __half2 h1 = __floats2half2_rn(a2, a3);
    float2 pk;
    pk.x = __uint_as_float(*reinterpret_cast<const unsigned int*>(&h0));
    pk.y = __uint_as_float(*reinterpret_cast<const unsigned int*>(&h1));
    *reinterpret_cast<float2*>(dst) = pk;
}

__device__ __forceinline__ void load4h(const __half2* src, float& x0, float& x1,
                                       float& x2, float& x3) {
    const float2 raw = *reinterpret_cast<const float2*>(src);
    const __half2 ha = *reinterpret_cast<const __half2*>(&raw.x);
    const __half2 hb = *reinterpret_cast<const __half2*>(&raw.y);
    const float2 fa = __half22float2(ha);
    const float2 fb = __half22float2(hb);
    x0 = fa.x; x1 = fa.y; x2 = fb.x; x3 = fb.y;
}

// m16n8k16 row.col f16xf16 -> f32 accumulate
__device__ __forceinline__ void mma16816(float* c, unsigned a0, unsigned a1,
                                         unsigned a2, unsigned a3,
                                         unsigned b0, unsigned b1) {
    asm volatile(
        "mma.sync.aligned.m16n8k16.row.col.f32.f16.f16.f32 "
        "{%0,%1,%2,%3}, {%4,%5,%6,%7}, {%8,%9}, {%0,%1,%2,%3};\n"
        : "+f"(c[0]), "+f"(c[1]), "+f"(c[2]), "+f"(c[3])
        : "r"(a0), "r"(a1), "r"(a2), "r"(a3), "r"(b0), "r"(b1));
}

__device__ __forceinline__ unsigned sptr(const void* p) {
    unsigned r;
    asm("{ .reg .u64 t; cvta.to.shared.u64 t, %1; cvt.u32.u64 %0, t; }"
        : "=r"(r) : "l"(p));
    return r;
}

__device__ __forceinline__ void ldmatrix_x4(unsigned& a0, unsigned& a1,
                                            unsigned& a2, unsigned& a3,
                                            unsigned addr) {
    asm volatile("ldmatrix.sync.aligned.m8n8.x4.shared.b16 {%0,%1,%2,%3}, [%4];"
                 : "=r"(a0), "=r"(a1), "=r"(a2), "=r"(a3) : "r"(addr));
}

__global__ void conv_weights_kernel(const float* __restrict__ W3l,
                                    const float* __restrict__ W2g,
                                    const float* __restrict__ W2l) {
    const int i = blockIdx.x * blockDim.x + threadIdx.x;
    if (i < 4096) {                       // W3l: 16 ntiles x 8 ks x 32 lanes
        const int lane = i & 31;
        const int r = lane >> 2, tq = lane & 3;
        const int nb = (i >> 8) * 8 + r;
        const int k0 = ((i >> 5) & 7) * 16 + tq * 2;
        g_W3lP[i * 2 + 0] = __floats2half2_rn(W3l[k0 * 128 + nb], W3l[(k0 + 1) * 128 + nb]);
        g_W3lP[i * 2 + 1] = __floats2half2_rn(W3l[(k0 + 8) * 128 + nb], W3l[(k0 + 9) * 128 + nb]);
    } else if (i < 6144) {                // W2g: 16 ntiles x 4 ks x 32 lanes
        const int j = i - 4096;
        const int lane = j & 31;
        const int r = lane >> 2, tq = lane & 3;
        const int nb = (j >> 7) * 8 + r;
        const int k0 = ((j >> 5) & 3) * 16 + tq * 2;
        g_W2gP[j * 2 + 0] = __floats2half2_rn(W2g[k0 * 128 + nb], W2g[(k0 + 1) * 128 + nb]);
        g_W2gP[j * 2 + 1] = __floats2half2_rn(W2g[(k0 + 8) * 128 + nb], W2g[(k0 + 9) * 128 + nb]);
    } else if (i < 6656) {                // W2l: 8 ntiles x 2 ks x 32 lanes
        const int j = i - 6144;
        const int lane = j & 31;
        const int r = lane >> 2, tq = lane & 3;
        const int nb = (j >> 6) * 8 + r;
        const int k0 = ((j >> 5) & 1) * 16 + tq * 2;
        g_W2lP[j * 2 + 0] = __floats2half2_rn(W2l[k0 * 64 + nb], W2l[(k0 + 1) * 64 + nb]);
        g_W2lP[j * 2 + 1] = __floats2half2_rn(W2l[(k0 + 8) * 64 + nb], W2l[(k0 + 9) * 64 + nb]);
    }
}

__global__ void __launch_bounds__(256, 3)
vae_fused_kernel(const float* __restrict__ rgb,  const float* __restrict__ pos,
                 const float* __restrict__ pos1, const float* __restrict__ pos2,
                 const int*   __restrict__ oi0,  const int* __restrict__ oi1,
                 const float* __restrict__ eps,
                 const float* __restrict__ W1l, const float* __restrict__ b1l,
                 const float* __restrict__ W1g, const float* __restrict__ b1g,
                 const float* __restrict__ W2l, const float* __restrict__ b2l,
                 const float* __restrict__ W2g, const float* __restrict__ b2g,
                 const float* __restrict__ W3l, const float* __restrict__ b3l,
                 const float* __restrict__ W3g, const float* __restrict__ b3g,
                 const float* __restrict__ Wlin, const float* __restrict__ blin,
                 float* __restrict__ out)
{
    extern __shared__ unsigned char smem_raw[];
    Smem& s = *reinterpret_cast<Smem*>(smem_raw);
    const int tid  = threadIdx.x;
    const int lane = tid & 31;
    const int g0   = blockIdx.x * 2;

    // ---------------- preamble ----------------------------------------------
    for (int i = tid; i < 64;  i += 256) s.w1l[i] = W1l[i];
    if (tid < 16) s.b1l[tid] = b1l[tid];
    if (tid < 32) s.b1g[tid] = b1g[tid];
    if (tid < 64) s.b2l[tid] = b2l[tid];
    for (int i = tid; i < 512; i += 256) s.w1g[i] = W1g[i];
    if (tid < 192) s.pos2l2[tid] = pos2[(size_t)g0 * 96 + tid];

    // ============ per-glimpse stages 1-3 ====================================
    for (int gi = 0; gi < 2; gi++) {
        const int g = g0 + gi;
        __syncthreads();
        if (tid < 128) s.cur[tid] = 0;
        if (tid < 32)  s.cur2[tid] = 0;
        for (int i = tid; i < 384; i += 256) s.pos1l[i] = pos1[(size_t)g * 384 + i];
        __syncthreads();

        // count phase
        if (tid < 128) {
            const int c2 = (int)(oi1[(size_t)g * 128 + tid] - g * CPG2);
            s.idx1[tid] = c2;
            atomicAdd(&s.cur2[c2], 1);
        }
        for (int p = tid; p < NPG; p += 256) {
            const size_t e = (size_t)g * NPG + p;
            float4 pt;
            pt.x = rgb[e];
            pt.y = pos[e * 3 + 0];
            pt.z = pos[e * 3 + 1];
            pt.w = pos[e * 3 + 2];
            s.B.pts[p] = pt;
            atomicAdd(&s.cur[oi0[e] - g * CPG], 1);
        }
        __syncthreads();

        // prefix sums; cur becomes alloc cursor
        if (tid < 32) {
            int v0 = s.cur[lane * 4 + 0], v1 = s.cur[lane * 4 + 1];
            int v2 = s.cur[lane * 4 + 2], v3 = s.cur[lane * 4 + 3];
            int lsum = v0 + v1 + v2 + v3;
            int sc = lsum;
            #pragma unroll
            for (int off = 1; off < 32; off <<= 1) {
                int n = __shfl_up_sync(0xffffffffu, sc, off);
                if (lane >= off) sc += n;
            }
            int e0 = sc - lsum;
            int e1 = e0 + v0, e2 = e1 + v1, e3 = e2 + v2;
            s.ofs[lane * 4 + 0] = (unsigned short)e0; s.cur[lane * 4 + 0] = e0;
            s.ofs[lane * 4 + 1] = (unsigned short)e1; s.cur[lane * 4 + 1] = e1;
            s.ofs[lane * 4 + 2] = (unsigned short)e2; s.cur[lane * 4 + 2] = e2;
            s.ofs[lane * 4 + 3] = (unsigned short)e3; s.cur[lane * 4 + 3] = e3;
        } else if (tid < 64) {
            int v = s.cur2[lane];
            int sc = v;
            #pragma unroll
            for (int off = 1; off < 32; off <<= 1) {
                int n = __shfl_up_sync(0xffffffffu, sc, off);
                if (lane >= off) sc += n;
            }
            s.ofs2[lane] = (unsigned short)(sc - v);
            s.cur2[lane] = sc - v;
        }
        __syncthreads();

        // scatter passes
        for (int p = tid; p < NPG; p += 256) {
            const int c = oi0[(size_t)g * NPG + p] - g * CPG;
            const int slot = atomicAdd(&s.cur[c], 1);
            s.order[slot] = (unsigned short)p;
        }
        if (tid < 128) {
            const int slot = atomicAdd(&s.cur2[s.idx1[tid]], 1);
            s.order2[slot] = (unsigned short)tid;
        }
        __syncthreads();

        // stage 1: gather edge MLP (4 -> 16) + mean
        {
            const int c    = tid >> 1;
            const int half = tid & 1;
            const int beg = (int)s.ofs[c];
            const int n   = s.cur[c] - beg;
            const float cx = s.pos1l[c * 3 + 0];
            const float cy = s.pos1l[c * 3 + 1];
            const float cz = s.pos1l[c * 3 + 2];
            float wb[8], w0r[8], w1r[8], w2r[8], w3r[8];
            #pragma unroll
            for (int j8 = 0; j8 < 8; j8++) {
                const int j = half * 8 + j8;
                wb[j8]  = s.b1l[j];
                w0r[j8] = s.w1l[j];
                w1r[j8] = s.w1l[16 + j];
                w2r[j8] = s.w1l[32 + j];
                w3r[j8] = s.w1l[48 + j];
            }
            float acc[8];
            #pragma unroll
            for (int j8 = 0; j8 < 8; j8++) acc[j8] = 0.0f;
            for (int i = 0; i < n; i++) {
                const float4 pt = s.B.pts[(int)s.order[beg + i]];
                const float rx = pt.y - cx, ry = pt.z - cy, rz = pt.w - cz;
                #pragma unroll
                for (int j8 = 0; j8 < 8; j8++) {
                    float a = wb[j8];
                    a = fmaf(pt.x, w0r[j8], a);
                    a = fmaf(rx,   w1r[j8], a);
                    a = fmaf(ry,   w2r[j8], a);
                    a = fmaf(rz,   w3r[j8], a);
                    acc[j8] += celu1(a);
                }
            }
            const float inv = 1.0f / fmaxf((float)n, 1.0f);
            #pragma unroll
            for (int j8 = 0; j8 < 8; j8++)
                s.agg[c * 16 + half * 8 + j8] = acc[j8] * inv;
        }
        __syncthreads();

        // stage 2: f1 = celu(mean1 @ W1g + b1g)  [128][32] -> fp16
        {
            const int jq = tid & 7;
            const int cg = tid >> 3;
            const float4* Wq = reinterpret_cast<const float4*>(s.w1g); // [16][8]
            float acc[4][4];
            #pragma unroll
            for (int c4 = 0; c4 < 4; c4++)
                #pragma unroll
                for (int u = 0; u < 4; u++) acc[c4][u] = s.b1g[jq * 4 + u];
            #pragma unroll
            for (int k = 0; k < 16; k++) {
                const float4 wv = Wq[k * 8 + jq];
                #pragma unroll
                for (int c4 = 0; c4 < 4; c4++) {
                    const float x = s.agg[(cg * 4 + c4) * 16 + k];
                    FMA4(acc[c4], x, wv);
                }
            }
            #pragma unroll
            for (int c4 = 0; c4 < 4; c4++) {
                const int c = cg * 4 + c4;
                pack2h2(celu1(acc[c4][0]), celu1(acc[c4][1]),
                        celu1(acc[c4][2]), celu1(acc[c4][3]),
                        &s.A.f1h[c * 16 + jq * 2]);
            }
        }
        __syncthreads();

        // stage 3a: edge MLP (35 -> 64) via tensor-core mma + ldmatrix --------
        {
            const int w  = tid >> 5;      // mtile 0..7
            const int r  = lane >> 2;
            const int tq = lane & 3;
            const int row0 = w * 16 + r;
            const int row1 = row0 + 8;
            const __half* Ah = reinterpret_cast<const __half*>(s.A.f1h);
            const unsigned abase =
                sptr(&Ah[(w * 16 + (lane & 15)) * 32 + ((lane & 16) ? 8 : 0)]);
            float c[8][4];
            #pragma unroll
            for (int nt = 0; nt < 8; nt++) {
                c[nt][0] = 0.f; c[nt][1] = 0.f; c[nt][2] = 0.f; c[nt][3] = 0.f;
            }
            #pragma unroll
            for (int ks = 0; ks < 2; ks++) {
                unsigned a0, a1, a2, a3;
                ldmatrix_x4(a0, a1, a2, a3, abase + ks * 32);
                #pragma unroll
                for (int nt = 0; nt < 8; nt++) {
                    const uint2 bb = *reinterpret_cast<const uint2*>(
                        &g_W2lP[((nt * 2 + ks) * 32 + lane) * 2]);
                    mma16816(c[nt], a0, a1, a2, a3, bb.x, bb.y);
                }
            }
            // epilogue: bias + relpos rows (32..34) + celu -> h2
            const int i0 = s.idx1[row0], i1 = s.idx1[row1];
            const float r00 = s.pos1l[row0 * 3 + 0] - s.pos2l2[gi * 96 + i0 * 3 + 0];
            const float r01 = s.pos1l[row0 * 3 + 1] - s.pos2l2[gi * 96 + i0 * 3 + 1];
            const float r02 = s.pos1l[row0 * 3 + 2] - s.pos2l2[gi * 96 + i0 * 3 + 2];
            const float r10 = s.pos1l[row1 * 3 + 0] - s.pos2l2[gi * 96 + i1 * 3 + 0];
            const float r11 = s.pos1l[row1 * 3 + 1] - s.pos2l2[gi * 96 + i1 * 3 + 1];
            const float r12 = s.pos1l[row1 * 3 + 2] - s.pos2l2[gi * 96 + i1 * 3 + 2];
            #pragma unroll
            for (int nt = 0; nt < 8; nt++) {
                const int nb0 = nt * 8 + tq * 2;
                const int nb1 = nb0 + 1;
                const float bi0 = s.b2l[nb0], bi1 = s.b2l[nb1];
                const float wa0 = W2l[32 * 64 + nb0], wa1 = W2l[32 * 64 + nb1];
                const float wb0 = W2l[33 * 64 + nb0], wb1 = W2l[33 * 64 + nb1];
                const float wc0 = W2l[34 * 64 + nb0], wc1 = W2l[34 * 64 + nb1];
                const float v00 = c[nt][0] + bi0 + r00 * wa0 + r01 * wb0 + r02 * wc0;
                const float v01 = c[nt][1] + bi1 + r00 * wa1 + r01 * wb1 + r02 * wc1;
                const float v10 = c[nt][2] + bi0 + r10 * wa0 + r11 * wb0 + r12 * wc0;
                const float v11 = c[nt][3] + bi1 + r10 * wa1 + r11 * wb1 + r12 * wc1;
                const int hcol = nt * 4 + tq;
                s.B.h2[row0 * 32 + hcol] = __floats2half2_rn(celu1(v00), celu1(v01));
                s.B.h2[row1 * 32 + hcol] = __floats2half2_rn(celu1(v10), celu1(v11));
            }
        }
        __syncthreads();

        // stage 3b: gather-reduce h2 -> mean2h[gi] [32][64] fp16
        {
            const int c2 = tid >> 3;
            const int f8 = tid & 7;
            const int beg = (int)s.ofs2[c2];
            const int n   = s.cur2[c2] - beg;
            float acc[8];
            #pragma unroll
            for (int k = 0; k < 8; k++) acc[k] = 0.0f;
            for (int i = 0; i < n; i++) {
                const int e = (int)s.order2[beg + i];
                float x0, x1, x2, x3, x4, x5, x6, x7;
                load4h(&s.B.h2[e * 32 + f8 * 4],     x0, x1, x2, x3);
                load4h(&s.B.h2[e * 32 + f8 * 4 + 2], x4, x5, x6, x7);
                acc[0] += x0; acc[1] += x1; acc[2] += x2; acc[3] += x3;
                acc[4] += x4; acc[5] += x5; acc[6] += x6; acc[7] += x7;
            }
            const float inv = 1.0f / fmaxf((float)n, 1.0f);
            pack2h2(acc[0] * inv, acc[1] * inv, acc[2] * inv, acc[3] * inv,
                    &s.mean2h[gi * 1024 + c2 * 32 + f8 * 4]);
            pack2h2(acc[4] * inv, acc[5] * inv, acc[6] * inv, acc[7] * inv,
                    &s.mean2h[gi * 1024 + c2 * 32 + f8 * 4 + 2]);
        }
    }
    __syncthreads();

    // ============ joint stages 4-7 ==========================================

    // stage 4: f2 = celu(mean2 @ W2g + b2g) via tensor-core mma + ldmatrix ----
    {
        const int w  = tid >> 5;
        const int m  = w & 3;
        const int nh = w >> 2;
        const int r  = lane >> 2;
        const int tq = lane & 3;
        const int row0 = m * 16 + r;
        const int row1 = row0 + 8;
        const __half* Ah = reinterpret_cast<const __half*>(s.mean2h);
        const unsigned abase =
            sptr(&Ah[(m * 16 + (lane & 15)) * 64 + ((lane & 16) ? 8 : 0)]);
        float c[8][4];
        #pragma unroll
        for (int nt = 0; nt < 8; nt++) {
            c[nt][0] = 0.f; c[nt][1] = 0.f; c[nt][2] = 0.f; c[nt][3] = 0.f;
        }
        #pragma unroll
        for (int ks = 0; ks < 4; ks++) {
            unsigned a0, a1, a2, a3;
            ldmatrix_x4(a0, a1, a2, a3, abase + ks * 32);
            #pragma unroll
            for (int nt = 0; nt < 8; nt++) {
                const uint2 bb = *reinterpret_cast<const uint2*>(
                    &g_W2gP[(((nh * 8 + nt) * 4 + ks) * 32 + lane) * 2]);
                mma16816(c[nt], a0, a1, a2, a3, bb.x, bb.y);
            }
        }
        #pragma unroll
        for (int nt = 0; nt < 8; nt++) {
            const int nb0 = nh * 64 + nt * 8 + tq * 2;
            const float bi0 = b2g[nb0], bi1 = b2g[nb0 + 1];
            const int hcol = nh * 32 + nt * 4 + tq;
            s.B.f2h[row0 * 64 + hcol] =
                __floats2half2_rn(celu1(c[nt][0] + bi0), celu1(c[nt][1] + bi1));
            s.B.f2h[row1 * 64 + hcol] =
                __floats2half2_rn(celu1(c[nt][2] + bi0), celu1(c[nt][3] + bi1));
        }
    }
    __syncthreads();

    // stage 5: level-3 edge MLP (131 -> 128) via tensor-core mma + ldmatrix --
    {
        const int w  = tid >> 5;
        const int m  = w & 3;
        const int nh = w >> 2;
        const int r  = lane >> 2;
        const int tq = lane & 3;
        const int rowA0 = m * 16 + r;
        const int rowA1 = rowA0 + 8;
        const __half* Ah = reinterpret_cast<const __half*>(s.B.f2h);
        const unsigned abase =
            sptr(&Ah[(m * 16 + (lane & 15)) * 128 + ((lane & 16) ? 8 : 0)]);
        float c[8][4];
        #pragma unroll
        for (int nt = 0; nt < 8; nt++) {
            c[nt][0] = 0.f; c[nt][1] = 0.f; c[nt][2] = 0.f; c[nt][3] = 0.f;
        }
        #pragma unroll
        for (int ks = 0; ks < 8; ks++) {
            unsigned a0, a1, a2, a3;
            ldmatrix_x4(a0, a1, a2, a3, abase + ks * 32);
            #pragma unroll
            for (int nt = 0; nt < 8; nt++) {
                const uint2 bb = *reinterpret_cast<const uint2*>(
                    &g_W3lP[(((nh * 8 + nt) * 8 + ks) * 32 + lane) * 2]);
                mma16816(c[nt], a0, a1, a2, a3, bb.x, bb.y);
            }
        }
        __syncthreads();   // all f2h reads done; B union becomes psum2
        const int gi = m >> 1;
        const int e0 = rowA0 & 31;
        const int e1 = rowA1 & 31;
        const float r00 = s.pos2l2[gi * 96 + e0 * 3 + 0];
        const float r01 = s.pos2l2[gi * 96 + e0 * 3 + 1];
        const float r02 = s.pos2l2[gi * 96 + e0 * 3 + 2];
        const float r10 = s.pos2l2[gi * 96 + e1 * 3 + 0];
        const float r11 = s.pos2l2[gi * 96 + e1 * 3 + 1];
        const float r12 = s.pos2l2[gi * 96 + e1 * 3 + 2];
        const int slot = (m & 1) * 8 + r;
        #pragma unroll
        for (int nt = 0; nt < 8; nt++) {
            const int nbase = nh * 64 + nt * 8 + tq * 2;
            float2 ov;
            #pragma unroll
            for (int u = 0; u < 2; u++) {
                const int n = nbase + u;
                const float bias = b3l[n];
                const float w0 = W3l[128 * 128 + n];
                const float w1 = W3l[129 * 128 + n];
                const float w2 = W3l[130 * 128 + n];
                const float v0 = c[nt][u]     + bias + r00 * w0 + r01 * w1 + r02 * w2;
                const float v1 = c[nt][2 + u] + bias + r10 * w0 + r11 * w1 + r12 * w2;
                ((float*)&ov)[u] = celu1(v0) + celu1(v1);
            }
            *reinterpret_cast<float2*>(&s.B.psum2[slot * 256 + gi * 128 + nbase]) = ov;
        }
    }
    __syncthreads();
    {
        const int gi = tid >> 7;
        const int j  = tid & 127;
        float sum = 0.0f;
        #pragma unroll
        for (int sl = 0; sl < 16; sl++) sum += s.B.psum2[sl * 256 + gi * 128 + j];
        s.gsum[gi * 128 + j] = sum;
    }
    __syncthreads();

    // stage 6: f = celu((gsum/32) @ W3g + b3g), both glimpses
    {
        const int j = tid;
        float s0 = 0.0f, s1 = 0.0f;
        #pragma unroll 8
        for (int k = 0; k < 128; k++) {
            const float w = W3g[k * 256 + j];
            s0 = fmaf(s.gsum[k],       w, s0);
            s1 = fmaf(s.gsum[128 + k], w, s1);
        }
        const float bj = b3g[j];
        const float f0 = celu1(fmaf(s0, 0.03125f, bj));
        const float f1 = celu1(fmaf(s1, 0.03125f, bj));
        s.fvec[j] = f0;
        s.fvec[256 + j] = f1;
        out[OFF_F + (size_t)g0 * 256 + j] = f0;
        out[OFF_F + (size_t)(g0 + 1) * 256 + j] = f1;
    }
    __syncthreads();

    // stage 7: out = f @ Wlin + blin, both glimpses
    {
        const int j = tid;
        const float bj = blin[j];
        float a0 = bj, a1 = bj;
        #pragma unroll 8
        for (int k = 0; k < 256; k++) {
            const float w = Wlin[k * 256 + j];
            a0 = fmaf(s.fvec[k],       w, a0);
            a1 = fmaf(s.fvec[256 + k], w, a1);
        }
        s.outv[j] = a0;
        s.outv[256 + j] = a1;
    }
    __syncthreads();

    if (tid < 128) {
        #pragma unroll
        for (int gi = 0; gi < 2; gi++) {
            const size_t g = g0 + gi;
            const float mu = s.outv[gi * 256 + tid];
            const float sg = s.outv[gi * 256 + 128 + tid];
            const float sigma = fmaxf(sg, 0.0f) + log1pf(__expf(-fabsf(sg)));
            const float z = fmaf(sigma, eps[g * 128 + tid], mu);
            out[OFF_MU    + g * 128 + tid] = mu;
            out[OFF_SIGMA + g * 128 + tid] = sigma;
            if (tid < 64) out[OFF_ZWHAT + g * 64 + tid] = z;
            else          out[OFF_ZMASK + g * 64 + (tid - 64)] = z;
        }
    }
}

extern "C" void kernel_launch(void* const* d_in, const int* in_sizes, int n_in,
                              void* d_out, int out_size)
{
    const float* rgb  = (const float*)d_in[0];
    const float* pos  = (const float*)d_in[1];
    const float* pos1 = (const float*)d_in[2];
    const float* pos2 = (const float*)d_in[3];
    const int*   oi0  = (const int*)  d_in[4];
    const int*   oi1  = (const int*)  d_in[5];
    const float* eps  = (const float*)d_in[7];
    const float* W1l  = (const float*)d_in[8];
    const float* b1l  = (const float*)d_in[9];
    const float* W1g  = (const float*)d_in[10];
    const float* b1g  = (const float*)d_in[11];
    const float* W2l  = (const float*)d_in[12];
    const float* b2l  = (const float*)d_in[13];
    const float* W2g  = (const float*)d_in[14];
    const float* b2g  = (const float*)d_in[15];
    const float* W3l  = (const float*)d_in[16];
    const float* b3l  = (const float*)d_in[17];
    const float* W3g  = (const float*)d_in[18];
    const float* b3g  = (const float*)d_in[19];
    const float* Wlin = (const float*)d_in[20];
    const float* blin = (const float*)d_in[21];
    float* out = (float*)d_out;

    conv_weights_kernel<<<26, 256>>>(W3l, W2g, W2l);

    cudaFuncSetAttribute(vae_fused_kernel,
                         cudaFuncAttributeMaxDynamicSharedMemorySize,
                         (int)sizeof(Smem));
    vae_fused_kernel<<<NG / 2, 256, sizeof(Smem)>>>(
        rgb, pos, pos1, pos2, oi0, oi1, eps,
        W1l, b1l, W1g, b1g, W2l, b2l, W2g, b2g,
        W3l, b3l, W3g, b3g, Wlin, blin, out);
}

// round 17
// speedup vs baseline: 3.4180x; 1.1504x over previous
#include <cuda_runtime.h>
#include <cuda_fp16.h>
#include <math.h>

// Problem constants
#define NG    2048
#define NPG   512
#define CPG   128
#define CPG2  32

// Output layout (float32)
#define OFF_ZWHAT 0
#define OFF_ZMASK 131072
#define OFF_MU    262144
#define OFF_SIGMA 524288
#define OFF_F     786432

// fp16 weights pre-packed in mma B-fragment order:
__device__ __half2 g_W3lP[16 * 8 * 32 * 2];
__device__ __half2 g_W2gP[16 * 4 * 32 * 2];
__device__ __half2 g_W2lP[8 * 2 * 32 * 2];
// fp16 col-quad packs for stages 6/7: [k][q] = 4 adjacent output cols
__device__ uint2 g_W3gH4[128 * 64];
__device__ uint2 g_WlinH4[256 * 64];

struct __align__(16) Smem {
    float w1l[64];      // [4][16]
    float b1l[16];
    float b1g[32];
    float b2l[64];
    float w1g[512];     // [16][32]
    float pos1l[384];   // [128][3]      (per-glimpse, reloaded)
    float pos2l2[192];  // [2][32][3]    (both glimpses)
    int   idx1[128];
    int   cur[128];
    int   cur2[32];
    unsigned short ofs[128];
    unsigned short ofs2[32];
    unsigned short order[512];
    unsigned short order2[128];
    float agg[2048];        // stage1 mean [128][16] (per-glimpse reuse)
    __half2 mean2h[2048];   // [2][32][32h2]
    float gsum[256];
    float fvec[512];
    float outv[512];
    union {                 // 8 KB (single-instance, per-glimpse reuse)
        __half2 f1h[2048];  // [128][16h2]
    } A;
    union {                 // 16 KB (single-instance, per-glimpse reuse)
        float4  pts[512];
        __half2 h2[4096];   // [128][32h2]
        __half2 f2h[4096];  // [2][32][64h2] joint stage4->5 (A operand for mma)
        float   psum2[4096];// stage-5 partials [16][256]; stage-6/7 partials [4][512]
    } B;
};

typedef unsigned long long u64t;

__device__ __forceinline__ float celu1(float x) {
    return fmaxf(x, 0.0f) + (__expf(fminf(x, 0.0f)) - 1.0f);
}

#define FMA4(Aacc, xs, wv) \
    { Aacc[0] = fmaf((xs), (wv).x, Aacc[0]); Aacc[1] = fmaf((xs), (wv).y, Aacc[1]); \
      Aacc[2] = fmaf((xs), (wv).z, Aacc[2]); Aacc[3] = fmaf((xs), (wv).w, Aacc[3]); }

__device__ __forceinline__ void pack2h2(float a0, float a1, float a2, float a3,
                                        __half2* dst) {
    const __half2 h0 = __floats2half2_rn(a0, a1);
    const __half2 h1 = __floats2half2_rn(a2, a3);
    float2 pk;
    pk.x = __uint_as_float(*reinterpret_cast<const unsigned int*>(&h0));
    pk.y = __uint_as_float(*reinterpret_cast<const unsigned int*>(&h1));
    *reinterpret_cast<float2*>(dst) = pk;
}

__device__ __forceinline__ void load4h(const __half2* src, float& x0, float& x1,
                                       float& x2, float& x3) {
    const float2 raw = *reinterpret_cast<const float2*>(src);
    const __half2 ha = *reinterpret_cast<const __half2*>(&raw.x);
    const __half2 hb = *reinterpret_cast<const __half2*>(&raw.y);
    const float2 fa = __half22float2(ha);
    const float2 fb = __half22float2(hb);
    x0 = fa.x; x1 = fa.y; x2 = fb.x; x3 = fb.y;
}

// m16n8k16 row.col f16xf16 -> f32 accumulate
__device__ __forceinline__ void mma16816(float* c, unsigned a0, unsigned a1,
                                         unsigned a2, unsigned a3,
                                         unsigned b0, unsigned b1) {
    asm volatile(
        "mma.sync.aligned.m16n8k16.row.col.f32.f16.f16.f32 "
        "{%0,%1,%2,%3}, {%4,%5,%6,%7}, {%8,%9}, {%0,%1,%2,%3};\n"
        : "+f"(c[0]), "+f"(c[1]), "+f"(c[2]), "+f"(c[3])
        : "r"(a0), "r"(a1), "r"(a2), "r"(a3), "r"(b0), "r"(b1));
}

__device__ __forceinline__ unsigned sptr(const void* p) {
    unsigned r;
    asm("{ .reg .u64 t; cvta.to.shared.u64 t, %1; cvt.u32.u64 %0, t; }"
        : "=r"(r) : "l"(p));
    return r;
}

__device__ __forceinline__ void ldmatrix_x4(unsigned& a0, unsigned& a1,
                                            unsigned& a2, unsigned& a3,
                                            unsigned addr) {
    asm volatile("ldmatrix.sync.aligned.m8n8.x4.shared.b16 {%0,%1,%2,%3}, [%4];"
                 : "=r"(a0), "=r"(a1), "=r"(a2), "=r"(a3) : "r"(addr));
}

__global__ void conv_weights_kernel(const float* __restrict__ W3l,
                                    const float* __restrict__ W2g,
                                    const float* __restrict__ W2l,
                                    const float* __restrict__ W3g,
                                    const float* __restrict__ Wlin) {
    const int i = blockIdx.x * blockDim.x + threadIdx.x;
    if (i < 4096) {                       // W3l: 16 ntiles x 8 ks x 32 lanes
        const int lane = i & 31;
        const int r = lane >> 2, tq = lane & 3;
        const int nb = (i >> 8) * 8 + r;
        const int k0 = ((i >> 5) & 7) * 16 + tq * 2;
        g_W3lP[i * 2 + 0] = __floats2half2_rn(W3l[k0 * 128 + nb], W3l[(k0 + 1) * 128 + nb]);
        g_W3lP[i * 2 + 1] = __floats2half2_rn(W3l[(k0 + 8) * 128 + nb], W3l[(k0 + 9) * 128 + nb]);
    } else if (i < 6144) {                // W2g: 16 ntiles x 4 ks x 32 lanes
        const int j = i - 4096;
        const int lane = j & 31;
        const int r = lane >> 2, tq = lane & 3;
        const int nb = (j >> 7) * 8 + r;
        const int k0 = ((j >> 5) & 3) * 16 + tq * 2;
        g_W2gP[j * 2 + 0] = __floats2half2_rn(W2g[k0 * 128 + nb], W2g[(k0 + 1) * 128 + nb]);
        g_W2gP[j * 2 + 1] = __floats2half2_rn(W2g[(k0 + 8) * 128 + nb], W2g[(k0 + 9) * 128 + nb]);
    } else if (i < 6656) {                // W2l: 8 ntiles x 2 ks x 32 lanes
        const int j = i - 6144;
        const int lane = j & 31;
        const int r = lane >> 2, tq = lane & 3;
        const int nb = (j >> 6) * 8 + r;
        const int k0 = ((j >> 5) & 1) * 16 + tq * 2;
        g_W2lP[j * 2 + 0] = __floats2half2_rn(W2l[k0 * 64 + nb], W2l[(k0 + 1) * 64 + nb]);
        g_W2lP[j * 2 + 1] = __floats2half2_rn(W2l[(k0 + 8) * 64 + nb], W2l[(k0 + 9) * 64 + nb]);
    } else if (i < 6656 + 8192) {         // W3g quads: [k 0..127][q 0..63]
        const int j = i - 6656;
        const int k = j >> 6, q = j & 63;
        const __half2 h0 = __floats2half2_rn(W3g[k * 256 + q * 4 + 0], W3g[k * 256 + q * 4 + 1]);
        const __half2 h1 = __floats2half2_rn(W3g[k * 256 + q * 4 + 2], W3g[k * 256 + q * 4 + 3]);
        uint2 v;
        v.x = *reinterpret_cast<const unsigned*>(&h0);
        v.y = *reinterpret_cast<const unsigned*>(&h1);
        g_W3gH4[j] = v;
    } else if (i < 6656 + 8192 + 16384) { // Wlin quads: [k 0..255][q 0..63]
        const int j = i - 14848;
        const int k = j >> 6, q = j & 63;
        const __half2 h0 = __floats2half2_rn(Wlin[k * 256 + q * 4 + 0], Wlin[k * 256 + q * 4 + 1]);
        const __half2 h1 = __floats2half2_rn(Wlin[k * 256 + q * 4 + 2], Wlin[k * 256 + q * 4 + 3]);
        uint2 v;
        v.x = *reinterpret_cast<const unsigned*>(&h0);
        v.y = *reinterpret_cast<const unsigned*>(&h1);
        g_WlinH4[j] = v;
    }
}

__global__ void __launch_bounds__(256, 3)
vae_fused_kernel(const float* __restrict__ rgb,  const float* __restrict__ pos,
                 const float* __restrict__ pos1, const float* __restrict__ pos2,
                 const int*   __restrict__ oi0,  const int* __restrict__ oi1,
                 const float* __restrict__ eps,
                 const float* __restrict__ W1l, const float* __restrict__ b1l,
                 const float* __restrict__ W1g, const float* __restrict__ b1g,
                 const float* __restrict__ W2l, const float* __restrict__ b2l,
                 const float* __restrict__ W2g, const float* __restrict__ b2g,
                 const float* __restrict__ W3l, const float* __restrict__ b3l,
                 const float* __restrict__ W3g, const float* __restrict__ b3g,
                 const float* __restrict__ Wlin, const float* __restrict__ blin,
                 float* __restrict__ out)
{
    extern __shared__ unsigned char smem_raw[];
    Smem& s = *reinterpret_cast<Smem*>(smem_raw);
    const int tid  = threadIdx.x;
    const int lane = tid & 31;
    const int g0   = blockIdx.x * 2;

    // ---------------- preamble ----------------------------------------------
    for (int i = tid; i < 64;  i += 256) s.w1l[i] = W1l[i];
    if (tid < 16) s.b1l[tid] = b1l[tid];
    if (tid < 32) s.b1g[tid] = b1g[tid];
    if (tid < 64) s.b2l[tid] = b2l[tid];
    for (int i = tid; i < 512; i += 256) s.w1g[i] = W1g[i];
    if (tid < 192) s.pos2l2[tid] = pos2[(size_t)g0 * 96 + tid];

    // ============ per-glimpse stages 1-3 ====================================
    for (int gi = 0; gi < 2; gi++) {
        const int g = g0 + gi;
        __syncthreads();
        if (tid < 128) s.cur[tid] = 0;
        if (tid < 32)  s.cur2[tid] = 0;
        for (int i = tid; i < 384; i += 256) s.pos1l[i] = pos1[(size_t)g * 384 + i];
        __syncthreads();

        // count phase
        if (tid < 128) {
            const int c2 = (int)(oi1[(size_t)g * 128 + tid] - g * CPG2);
            s.idx1[tid] = c2;
            atomicAdd(&s.cur2[c2], 1);
        }
        for (int p = tid; p < NPG; p += 256) {
            const size_t e = (size_t)g * NPG + p;
            float4 pt;
            pt.x = rgb[e];
            pt.y = pos[e * 3 + 0];
            pt.z = pos[e * 3 + 1];
            pt.w = pos[e * 3 + 2];
            s.B.pts[p] = pt;
            atomicAdd(&s.cur[oi0[e] - g * CPG], 1);
        }
        __syncthreads();

        // prefix sums; cur becomes alloc cursor
        if (tid < 32) {
            int v0 = s.cur[lane * 4 + 0], v1 = s.cur[lane * 4 + 1];
            int v2 = s.cur[lane * 4 + 2], v3 = s.cur[lane * 4 + 3];
            int lsum = v0 + v1 + v2 + v3;
            int sc = lsum;
            #pragma unroll
            for (int off = 1; off < 32; off <<= 1) {
                int n = __shfl_up_sync(0xffffffffu, sc, off);
                if (lane >= off) sc += n;
            }
            int e0 = sc - lsum;
            int e1 = e0 + v0, e2 = e1 + v1, e3 = e2 + v2;
            s.ofs[lane * 4 + 0] = (unsigned short)e0; s.cur[lane * 4 + 0] = e0;
            s.ofs[lane * 4 + 1] = (unsigned short)e1; s.cur[lane * 4 + 1] = e1;
            s.ofs[lane * 4 + 2] = (unsigned short)e2; s.cur[lane * 4 + 2] = e2;
            s.ofs[lane * 4 + 3] = (unsigned short)e3; s.cur[lane * 4 + 3] = e3;
        } else if (tid < 64) {
            int v = s.cur2[lane];
            int sc = v;
            #pragma unroll
            for (int off = 1; off < 32; off <<= 1) {
                int n = __shfl_up_sync(0xffffffffu, sc, off);
                if (lane >= off) sc += n;
            }
            s.ofs2[lane] = (unsigned short)(sc - v);
            s.cur2[lane] = sc - v;
        }
        __syncthreads();

        // scatter passes
        for (int p = tid; p < NPG; p += 256) {
            const int c = oi0[(size_t)g * NPG + p] - g * CPG;
            const int slot = atomicAdd(&s.cur[c], 1);
            s.order[slot] = (unsigned short)p;
        }
        if (tid < 128) {
            const int slot = atomicAdd(&s.cur2[s.idx1[tid]], 1);
            s.order2[slot] = (unsigned short)tid;
        }
        __syncthreads();

        // stage 1: gather edge MLP (4 -> 16) + mean
        {
            const int c    = tid >> 1;
            const int half = tid & 1;
            const int beg = (int)s.ofs[c];
            const int n   = s.cur[c] - beg;
            const float cx = s.pos1l[c * 3 + 0];
            const float cy = s.pos1l[c * 3 + 1];
            const float cz = s.pos1l[c * 3 + 2];
            float wb[8], w0r[8], w1r[8], w2r[8], w3r[8];
            #pragma unroll
            for (int j8 = 0; j8 < 8; j8++) {
                const int j = half * 8 + j8;
                wb[j8]  = s.b1l[j];
                w0r[j8] = s.w1l[j];
                w1r[j8] = s.w1l[16 + j];
                w2r[j8] = s.w1l[32 + j];
                w3r[j8] = s.w1l[48 + j];
            }
            float acc[8];
            #pragma unroll
            for (int j8 = 0; j8 < 8; j8++) acc[j8] = 0.0f;
            for (int i = 0; i < n; i++) {
                const float4 pt = s.B.pts[(int)s.order[beg + i]];
                const float rx = pt.y - cx, ry = pt.z - cy, rz = pt.w - cz;
                #pragma unroll
                for (int j8 = 0; j8 < 8; j8++) {
                    float a = wb[j8];
                    a = fmaf(pt.x, w0r[j8], a);
                    a = fmaf(rx,   w1r[j8], a);
                    a = fmaf(ry,   w2r[j8], a);
                    a = fmaf(rz,   w3r[j8], a);
                    acc[j8] += celu1(a);
                }
            }
            const float inv = 1.0f / fmaxf((float)n, 1.0f);
            #pragma unroll
            for (int j8 = 0; j8 < 8; j8++)
                s.agg[c * 16 + half * 8 + j8] = acc[j8] * inv;
        }
        __syncthreads();

        // stage 2: f1 = celu(mean1 @ W1g + b1g)  [128][32] -> fp16
        {
            const int jq = tid & 7;
            const int cg = tid >> 3;
            const float4* Wq = reinterpret_cast<const float4*>(s.w1g); // [16][8]
            float acc[4][4];
            #pragma unroll
            for (int c4 = 0; c4 < 4; c4++)
                #pragma unroll
                for (int u = 0; u < 4; u++) acc[c4][u] = s.b1g[jq * 4 + u];
            #pragma unroll
            for (int k = 0; k < 16; k++) {
                const float4 wv = Wq[k * 8 + jq];
                #pragma unroll
                for (int c4 = 0; c4 < 4; c4++) {
                    const float x = s.agg[(cg * 4 + c4) * 16 + k];
                    FMA4(acc[c4], x, wv);
                }
            }
            #pragma unroll
            for (int c4 = 0; c4 < 4; c4++) {
                const int c = cg * 4 + c4;
                pack2h2(celu1(acc[c4][0]), celu1(acc[c4][1]),
                        celu1(acc[c4][2]), celu1(acc[c4][3]),
                        &s.A.f1h[c * 16 + jq * 2]);
            }
        }
        __syncthreads();

        // stage 3a: edge MLP (35 -> 64) via tensor-core mma + ldmatrix --------
        {
            const int w  = tid >> 5;      // mtile 0..7
            const int r  = lane >> 2;
            const int tq = lane & 3;
            const int row0 = w * 16 + r;
            const int row1 = row0 + 8;
            const __half* Ah = reinterpret_cast<const __half*>(s.A.f1h);
            const unsigned abase =
                sptr(&Ah[(w * 16 + (lane & 15)) * 32 + ((lane & 16) ? 8 : 0)]);
            float c[8][4];
            #pragma unroll
            for (int nt = 0; nt < 8; nt++) {
                c[nt][0] = 0.f; c[nt][1] = 0.f; c[nt][2] = 0.f; c[nt][3] = 0.f;
            }
            #pragma unroll
            for (int ks = 0; ks < 2; ks++) {
                unsigned a0, a1, a2, a3;
                ldmatrix_x4(a0, a1, a2, a3, abase + ks * 32);
                #pragma unroll
                for (int nt = 0; nt < 8; nt++) {
                    const uint2 bb = *reinterpret_cast<const uint2*>(
                        &g_W2lP[((nt * 2 + ks) * 32 + lane) * 2]);
                    mma16816(c[nt], a0, a1, a2, a3, bb.x, bb.y);
                }
            }
            // epilogue: bias + relpos rows (32..34) + celu -> h2
            const int i0 = s.idx1[row0], i1 = s.idx1[row1];
            const float r00 = s.pos1l[row0 * 3 + 0] - s.pos2l2[gi * 96 + i0 * 3 + 0];
            const float r01 = s.pos1l[row0 * 3 + 1] - s.pos2l2[gi * 96 + i0 * 3 + 1];
            const float r02 = s.pos1l[row0 * 3 + 2] - s.pos2l2[gi * 96 + i0 * 3 + 2];
            const float r10 = s.pos1l[row1 * 3 + 0] - s.pos2l2[gi * 96 + i1 * 3 + 0];
            const float r11 = s.pos1l[row1 * 3 + 1] - s.pos2l2[gi * 96 + i1 * 3 + 1];
            const float r12 = s.pos1l[row1 * 3 + 2] - s.pos2l2[gi * 96 + i1 * 3 + 2];
            #pragma unroll
            for (int nt = 0; nt < 8; nt++) {
                const int nb0 = nt * 8 + tq * 2;
                const int nb1 = nb0 + 1;
                const float bi0 = s.b2l[nb0], bi1 = s.b2l[nb1];
                const float wa0 = W2l[32 * 64 + nb0], wa1 = W2l[32 * 64 + nb1];
                const float wb0 = W2l[33 * 64 + nb0], wb1 = W2l[33 * 64 + nb1];
                const float wc0 = W2l[34 * 64 + nb0], wc1 = W2l[34 * 64 + nb1];
                const float v00 = c[nt][0] + bi0 + r00 * wa0 + r01 * wb0 + r02 * wc0;
                const float v01 = c[nt][1] + bi1 + r00 * wa1 + r01 * wb1 + r02 * wc1;
                const float v10 = c[nt][2] + bi0 + r10 * wa0 + r11 * wb0 + r12 * wc0;
                const float v11 = c[nt][3] + bi1 + r10 * wa1 + r11 * wb1 + r12 * wc1;
                const int hcol = nt * 4 + tq;
                s.B.h2[row0 * 32 + hcol] = __floats2half2_rn(celu1(v00), celu1(v01));
                s.B.h2[row1 * 32 + hcol] = __floats2half2_rn(celu1(v10), celu1(v11));
            }
        }
        __syncthreads();

        // stage 3b: gather-reduce h2 -> mean2h[gi] [32][64] fp16
        {
            const int c2 = tid >> 3;
            const int f8 = tid & 7;
            const int beg = (int)s.ofs2[c2];
            const int n   = s.cur2[c2] - beg;
            float acc[8];
            #pragma unroll
            for (int k = 0; k < 8; k++) acc[k] = 0.0f;
            for (int i = 0; i < n; i++) {
                const int e = (int)s.order2[beg + i];
                float x0, x1, x2, x3, x4, x5, x6, x7;
                load4h(&s.B.h2[e * 32 + f8 * 4],     x0, x1, x2, x3);
                load4h(&s.B.h2[e * 32 + f8 * 4 + 2], x4, x5, x6, x7);
                acc[0] += x0; acc[1] += x1; acc[2] += x2; acc[3] += x3;
                acc[4] += x4; acc[5] += x5; acc[6] += x6; acc[7] += x7;
            }
            const float inv = 1.0f / fmaxf((float)n, 1.0f);
            pack2h2(acc[0] * inv, acc[1] * inv, acc[2] * inv, acc[3] * inv,
                    &s.mean2h[gi * 1024 + c2 * 32 + f8 * 4]);
            pack2h2(acc[4] * inv, acc[5] * inv, acc[6] * inv, acc[7] * inv,
                    &s.mean2h[gi * 1024 + c2 * 32 + f8 * 4 + 2]);
        }
    }
    __syncthreads();

    // ============ joint stages 4-7 ==========================================

    // stage 4: f2 = celu(mean2 @ W2g + b2g) via tensor-core mma + ldmatrix ----
    {
        const int w  = tid >> 5;
        const int m  = w & 3;
        const int nh = w >> 2;
        const int r  = lane >> 2;
        const int tq = lane & 3;
        const int row0 = m * 16 + r;
        const int row1 = row0 + 8;
        const __half* Ah = reinterpret_cast<const __half*>(s.mean2h);
        const unsigned abase =
            sptr(&Ah[(m * 16 + (lane & 15)) * 64 + ((lane & 16) ? 8 : 0)]);
        float c[8][4];
        #pragma unroll
        for (int nt = 0; nt < 8; nt++) {
            c[nt][0] = 0.f; c[nt][1] = 0.f; c[nt][2] = 0.f; c[nt][3] = 0.f;
        }
        #pragma unroll
        for (int ks = 0; ks < 4; ks++) {
            unsigned a0, a1, a2, a3;
            ldmatrix_x4(a0, a1, a2, a3, abase + ks * 32);
            #pragma unroll
            for (int nt = 0; nt < 8; nt++) {
                const uint2 bb = *reinterpret_cast<const uint2*>(
                    &g_W2gP[(((nh * 8 + nt) * 4 + ks) * 32 + lane) * 2]);
                mma16816(c[nt], a0, a1, a2, a3, bb.x, bb.y);
            }
        }
        #pragma unroll
        for (int nt = 0; nt < 8; nt++) {
            const int nb0 = nh * 64 + nt * 8 + tq * 2;
            const float bi0 = b2g[nb0], bi1 = b2g[nb0 + 1];
            const int hcol = nh * 32 + nt * 4 + tq;
            s.B.f2h[row0 * 64 + hcol] =
                __floats2half2_rn(celu1(c[nt][0] + bi0), celu1(c[nt][1] + bi1));
            s.B.f2h[row1 * 64 + hcol] =
                __floats2half2_rn(celu1(c[nt][2] + bi0), celu1(c[nt][3] + bi1));
        }
    }
    __syncthreads();

    // stage 5: level-3 edge MLP (131 -> 128) via tensor-core mma + ldmatrix --
    {
        const int w  = tid >> 5;
        const int m  = w & 3;
        const int nh = w >> 2;
        const int r  = lane >> 2;
        const int tq = lane & 3;
        const int rowA0 = m * 16 + r;
        const int rowA1 = rowA0 + 8;
        const __half* Ah = reinterpret_cast<const __half*>(s.B.f2h);
        const unsigned abase =
            sptr(&Ah[(m * 16 + (lane & 15)) * 128 + ((lane & 16) ? 8 : 0)]);
        float c[8][4];
        #pragma unroll
        for (int nt = 0; nt < 8; nt++) {
            c[nt][0] = 0.f; c[nt][1] = 0.f; c[nt][2] = 0.f; c[nt][3] = 0.f;
        }
        #pragma unroll
        for (int ks = 0; ks < 8; ks++) {
            unsigned a0, a1, a2, a3;
            ldmatrix_x4(a0, a1, a2, a3, abase + ks * 32);
            #pragma unroll
            for (int nt = 0; nt < 8; nt++) {
                const uint2 bb = *reinterpret_cast<const uint2*>(
                    &g_W3lP[(((nh * 8 + nt) * 8 + ks) * 32 + lane) * 2]);
                mma16816(c[nt], a0, a1, a2, a3, bb.x, bb.y);
            }
        }
        __syncthreads();   // all f2h reads done; B union becomes psum2
        const int gi = m >> 1;
        const int e0 = rowA0 & 31;
        const int e1 = rowA1 & 31;
        const float r00 = s.pos2l2[gi * 96 + e0 * 3 + 0];
        const float r01 = s.pos2l2[gi * 96 + e0 * 3 + 1];
        const float r02 = s.pos2l2[gi * 96 + e0 * 3 + 2];
        const float r10 = s.pos2l2[gi * 96 + e1 * 3 + 0];
        const float r11 = s.pos2l2[gi * 96 + e1 * 3 + 1];
        const float r12 = s.pos2l2[gi * 96 + e1 * 3 + 2];
        const int slot = (m & 1) * 8 + r;
        #pragma unroll
        for (int nt = 0; nt < 8; nt++) {
            const int nbase = nh * 64 + nt * 8 + tq * 2;
            float2 ov;
            #pragma unroll
            for (int u = 0; u < 2; u++) {
                const int n = nbase + u;
                const float bias = b3l[n];
                const float w0 = W3l[128 * 128 + n];
                const float w1 = W3l[129 * 128 + n];
                const float w2 = W3l[130 * 128 + n];
                const float v0 = c[nt][u]     + bias + r00 * w0 + r01 * w1 + r02 * w2;
                const float v1 = c[nt][2 + u] + bias + r10 * w0 + r11 * w1 + r12 * w2;
                ((float*)&ov)[u] = celu1(v0) + celu1(v1);
            }
            *reinterpret_cast<float2*>(&s.B.psum2[slot * 256 + gi * 128 + nbase]) = ov;
        }
    }
    __syncthreads();
    {
        const int gi = tid >> 7;
        const int j  = tid & 127;
        float sum = 0.0f;
        #pragma unroll
        for (int sl = 0; sl < 16; sl++) sum += s.B.psum2[sl * 256 + gi * 128 + j];
        s.gsum[gi * 128 + j] = sum;
    }
    __syncthreads();

    // stage 6: f = celu((gsum/32) @ W3g + b3g), fp16 quads, k-split(4) --------
    {
        const int kh = tid >> 6;   // 0..3
        const int q  = tid & 63;   // col quad
        float a0[4] = {0.f, 0.f, 0.f, 0.f};
        float a1[4] = {0.f, 0.f, 0.f, 0.f};
        const int kbeg = kh * 32;
        #pragma unroll 8
        for (int k = kbeg; k < kbeg + 32; k++) {
            const uint2 wv = g_W3gH4[k * 64 + q];
            const float2 wA = __half22float2(*reinterpret_cast<const __half2*>(&wv.x));
            const float2 wB = __half22float2(*reinterpret_cast<const __half2*>(&wv.y));
            const float f0 = s.gsum[k];
            const float f1 = s.gsum[128 + k];
            a0[0] = fmaf(f0, wA.x, a0[0]); a0[1] = fmaf(f0, wA.y, a0[1]);
            a0[2] = fmaf(f0, wB.x, a0[2]); a0[3] = fmaf(f0, wB.y, a0[3]);
            a1[0] = fmaf(f1, wA.x, a1[0]); a1[1] = fmaf(f1, wA.y, a1[1]);
            a1[2] = fmaf(f1, wB.x, a1[2]); a1[3] = fmaf(f1, wB.y, a1[3]);
        }
        float4 v0, v1;
        v0.x = a0[0]; v0.y = a0[1]; v0.z = a0[2]; v0.w = a0[3];
        v1.x = a1[0]; v1.y = a1[1]; v1.z = a1[2]; v1.w = a1[3];
        *reinterpret_cast<float4*>(&s.B.psum2[kh * 512 + q * 4])       = v0;
        *reinterpret_cast<float4*>(&s.B.psum2[kh * 512 + 256 + q * 4]) = v1;
    }
    __syncthreads();
    {
        for (int o = tid; o < 512; o += 256) {
            const float sum = s.B.psum2[o] + s.B.psum2[512 + o]
                            + s.B.psum2[1024 + o] + s.B.psum2[1536 + o];
            const int gi = o >> 8, j = o & 255;
            const float fv = celu1(fmaf(sum, 0.03125f, b3g[j]));
            s.fvec[gi * 256 + j] = fv;
            out[OFF_F + (size_t)(g0 + gi) * 256 + j] = fv;
        }
    }
    __syncthreads();

    // stage 7: out = f @ Wlin + blin, fp16 quads, k-split(4) ------------------
    {
        const int kh = tid >> 6;
        const int q  = tid & 63;
        float a0[4] = {0.f, 0.f, 0.f, 0.f};
        float a1[4] = {0.f, 0.f, 0.f, 0.f};
        const int kbeg = kh * 64;
        #pragma unroll 8
        for (int k = kbeg; k < kbeg + 64; k++) {
            const uint2 wv = g_WlinH4[k * 64 + q];
            const float2 wA = __half22float2(*reinterpret_cast<const __half2*>(&wv.x));
            const float2 wB = __half22float2(*reinterpret_cast<const __half2*>(&wv.y));
            const float f0 = s.fvec[k];
            const float f1 = s.fvec[256 + k];
            a0[0] = fmaf(f0, wA.x, a0[0]); a0[1] = fmaf(f0, wA.y, a0[1]);
            a0[2] = fmaf(f0, wB.x, a0[2]); a0[3] = fmaf(f0, wB.y, a0[3]);
            a1[0] = fmaf(f1, wA.x, a1[0]); a1[1] = fmaf(f1, wA.y, a1[1]);
            a1[2] = fmaf(f1, wB.x, a1[2]); a1[3] = fmaf(f1, wB.y, a1[3]);
        }
        __syncthreads();   // stage-6 reduce reads of psum2 are complete
        float4 v0, v1;
        v0.x = a0[0]; v0.y = a0[1]; v0.z = a0[2]; v0.w = a0[3];
        v1.x = a1[0]; v1.y = a1[1]; v1.z = a1[2]; v1.w = a1[3];
        *reinterpret_cast<float4*>(&s.B.psum2[kh * 512 + q * 4])       = v0;
        *reinterpret_cast<float4*>(&s.B.psum2[kh * 512 + 256 + q * 4]) = v1;
    }
    __syncthreads();
    {
        for (int o = tid; o < 512; o += 256) {
            const float sum = s.B.psum2[o] + s.B.psum2[512 + o]
                            + s.B.psum2[1024 + o] + s.B.psum2[1536 + o];
            s.outv[o] = sum + blin[o & 255];
        }
    }
    __syncthreads();

    if (tid < 128) {
        #pragma unroll
        for (int gi = 0; gi < 2; gi++) {
            const size_t g = g0 + gi;
            const float mu = s.outv[gi * 256 + tid];
            const float sg = s.outv[gi * 256 + 128 + tid];
            const float sigma = fmaxf(sg, 0.0f) + log1pf(__expf(-fabsf(sg)));
            const float z = fmaf(sigma, eps[g * 128 + tid], mu);
            out[OFF_MU    + g * 128 + tid] = mu;
            out[OFF_SIGMA + g * 128 + tid] = sigma;
            if (tid < 64) out[OFF_ZWHAT + g * 64 + tid] = z;
            else          out[OFF_ZMASK + g * 64 + (tid - 64)] = z;
        }
    }
}

extern "C" void kernel_launch(void* const* d_in, const int* in_sizes, int n_in,
                              void* d_out, int out_size)
{
    const float* rgb  = (const float*)d_in[0];
    const float* pos  = (const float*)d_in[1];
    const float* pos1 = (const float*)d_in[2];
    const float* pos2 = (const float*)d_in[3];
    const int*   oi0  = (const int*)  d_in[4];
    const int*   oi1  = (const int*)  d_in[5];
    const float* eps  = (const float*)d_in[7];
    const float* W1l  = (const float*)d_in[8];
    const float* b1l  = (const float*)d_in[9];
    const float* W1g  = (const float*)d_in[10];
    const float* b1g  = (const float*)d_in[11];
    const float* W2l  = (const float*)d_in[12];
    const float* b2l  = (const float*)d_in[13];
    const float* W2g  = (const float*)d_in[14];
    const float* b2g  = (const float*)d_in[15];
    const float* W3l  = (const float*)d_in[16];
    const float* b3l  = (const float*)d_in[17];
    const float* W3g  = (const float*)d_in[18];
    const float* b3g  = (const float*)d_in[19];
    const float* Wlin = (const float*)d_in[20];
    const float* blin = (const float*)d_in[21];
    float* out = (float*)d_out;

    conv_weights_kernel<<<122, 256>>>(W3l, W2g, W2l, W3g, Wlin);

    cudaFuncSetAttribute(vae_fused_kernel,
                         cudaFuncAttributeMaxDynamicSharedMemorySize,
                         (int)sizeof(Smem));
    vae_fused_kernel<<<NG / 2, 256, sizeof(Smem)>>>(
        rgb, pos, pos1, pos2, oi0, oi1, eps,
        W1l, b1l, W1g, b1g, W2l, b2l, W2g, b2g,
        W3l, b3l, W3g, b3g, Wlin, blin, out);
}